// round 2
// baseline (speedup 1.0000x reference)
#include <cuda_runtime.h>
#include <math.h>

#define G 128
#define G3 (G*G*G)

// Ping-pong scratch (no cudaMalloc allowed).
// bufB holds the largest tensor: conv1 out = 32*128^3 = 67,108,864 floats (268MB)
// bufA max: conv2/conv3 tensors = 64*64^3 = 16,777,216 floats (67MB)
__device__ float g_bufA[16777216];
__device__ float g_bufB[67108864];

// ---------------------------------------------------------------- utilities
__global__ void zero_kernel(float* __restrict__ p, int n) {
    int i = blockIdx.x * blockDim.x + threadIdx.x;
    if (i < n) p[i] = 0.f;
}

// ---------------------------------------------------------------- voxelize
// grid layout: (4, z, y, x), scatter-ADD of (x,y,z,intensity)
__global__ void voxelize_kernel(const float4* __restrict__ pts, float* __restrict__ grid, int N) {
    int i = blockIdx.x * blockDim.x + threadIdx.x;
    if (i >= N) return;
    float4 p = pts[i];
    if (p.x < -32.f || p.x > 32.f ||
        p.y < -32.f || p.y > 32.f ||
        p.z < -32.f || p.z > 32.f) return;
    int cx = (int)floorf((p.x + 32.f) * 2.f);
    int cy = (int)floorf((p.y + 32.f) * 2.f);
    int cz = (int)floorf((p.z + 32.f) * 2.f);
    cx = cx < 0 ? 0 : (cx > G-1 ? G-1 : cx);
    cy = cy < 0 ? 0 : (cy > G-1 ? G-1 : cy);
    cz = cz < 0 ? 0 : (cz > G-1 ? G-1 : cz);
    int base = (cz * G + cy) * G + cx;
    atomicAdd(&grid[0*G3 + base], p.x);
    atomicAdd(&grid[1*G3 + base], p.y);
    atomicAdd(&grid[2*G3 + base], p.z);
    atomicAdd(&grid[3*G3 + base], p.w);
}

// ---------------------------------------------------------------- conv3d + BN + ReLU
// Direct conv, NCDHW cubic tensors. Block: 128 threads = 4x4x8 spatial outputs,
// 16 output channels per block (blockIdx.y). Loop over input channels; per ci:
// smem input tile + smem weight tile transposed [tap][oc] for float4 broadcast reads.
template<int CI, int STRIDE>
__global__ void __launch_bounds__(128)
conv_bn_relu_kernel(const float* __restrict__ in, const float* __restrict__ wgt,
                    const float* __restrict__ gamma, const float* __restrict__ beta,
                    float* __restrict__ out, int Sin, int Sout)
{
    constexpr int TZ = 4, TY = 4, TX = 8;
    constexpr int ITZ = (TZ-1)*STRIDE + 3;
    constexpr int ITY = (TY-1)*STRIDE + 3;
    constexpr int ITX = (TX-1)*STRIDE + 3;
    constexpr int ITOT = ITZ * ITY * ITX;

    __shared__ float s_in[ITOT];
    __shared__ float s_w[27 * 16];

    const int tid = threadIdx.x;
    const int lx = tid & 7;
    const int ly = (tid >> 3) & 3;
    const int lz = tid >> 5;

    const int ntx = Sout / TX, nty = Sout / TY;
    int bt = blockIdx.x;
    const int tx0 = (bt % ntx) * TX; bt /= ntx;
    const int ty0 = (bt % nty) * TY; bt /= nty;
    const int tz0 = bt * TZ;
    const int oc0 = blockIdx.y * 16;

    const int bz = tz0 * STRIDE - 1;
    const int by = ty0 * STRIDE - 1;
    const int bx = tx0 * STRIDE - 1;

    float acc[16];
#pragma unroll
    for (int i = 0; i < 16; i++) acc[i] = 0.f;

    for (int ci = 0; ci < CI; ci++) {
        const float* inc = in + (size_t)ci * Sin * Sin * Sin;
        // load input tile (zero padded)
        for (int idx = tid; idx < ITOT; idx += 128) {
            int ix = idx % ITX;
            int t  = idx / ITX;
            int iy = t % ITY;
            int iz = t / ITY;
            int gz = bz + iz, gy = by + iy, gx = bx + ix;
            float v = 0.f;
            if ((unsigned)gz < (unsigned)Sin && (unsigned)gy < (unsigned)Sin &&
                (unsigned)gx < (unsigned)Sin)
                v = inc[(gz * Sin + gy) * Sin + gx];
            s_in[idx] = v;
        }
        // load weights transposed: s_w[t*16+oc] = wgt[((oc0+oc)*CI+ci)*27 + t]
        for (int idx = tid; idx < 432; idx += 128) {
            int oc = idx / 27;
            int t  = idx - oc * 27;
            s_w[t * 16 + oc] = wgt[((size_t)(oc0 + oc) * CI + ci) * 27 + t];
        }
        __syncthreads();

        const int iz0 = lz * STRIDE, iy0 = ly * STRIDE, ix0 = lx * STRIDE;
#pragma unroll
        for (int dz = 0; dz < 3; dz++)
#pragma unroll
        for (int dy = 0; dy < 3; dy++)
#pragma unroll
        for (int dx = 0; dx < 3; dx++) {
            const float v = s_in[((iz0 + dz) * ITY + (iy0 + dy)) * ITX + (ix0 + dx)];
            const int t = (dz * 3 + dy) * 3 + dx;
            const float4* wv = (const float4*)&s_w[t * 16];
            const float4 w0 = wv[0], w1 = wv[1], w2 = wv[2], w3 = wv[3];
            acc[ 0] = fmaf(v, w0.x, acc[ 0]);
            acc[ 1] = fmaf(v, w0.y, acc[ 1]);
            acc[ 2] = fmaf(v, w0.z, acc[ 2]);
            acc[ 3] = fmaf(v, w0.w, acc[ 3]);
            acc[ 4] = fmaf(v, w1.x, acc[ 4]);
            acc[ 5] = fmaf(v, w1.y, acc[ 5]);
            acc[ 6] = fmaf(v, w1.z, acc[ 6]);
            acc[ 7] = fmaf(v, w1.w, acc[ 7]);
            acc[ 8] = fmaf(v, w2.x, acc[ 8]);
            acc[ 9] = fmaf(v, w2.y, acc[ 9]);
            acc[10] = fmaf(v, w2.z, acc[10]);
            acc[11] = fmaf(v, w2.w, acc[11]);
            acc[12] = fmaf(v, w3.x, acc[12]);
            acc[13] = fmaf(v, w3.y, acc[13]);
            acc[14] = fmaf(v, w3.z, acc[14]);
            acc[15] = fmaf(v, w3.w, acc[15]);
        }
        __syncthreads();
    }

    // epilogue: eval-mode BN (mean 0, var 1) + ReLU
    const int oz = tz0 + lz, oy = ty0 + ly, ox = tx0 + lx;
    const size_t sp = ((size_t)oz * Sout + oy) * Sout + ox;
    const float inv = rsqrtf(1.f + 1e-5f);
#pragma unroll
    for (int oc = 0; oc < 16; oc++) {
        const int ocg = oc0 + oc;
        float val = acc[oc] * (gamma[ocg] * inv) + beta[ocg];
        out[(size_t)ocg * Sout * Sout * Sout + sp] = val > 0.f ? val : 0.f;
    }
}

// ---------------------------------------------------------------- BEV max over H (y)
// feat (256, 32, 32, 32) -> bev (256, 32, 32): bev[c][z][x] = max_y feat[c][z][y][x]
__global__ void bevmax_kernel(const float* __restrict__ feat, float* __restrict__ bev) {
    int i = blockIdx.x * blockDim.x + threadIdx.x;
    if (i >= 256 * 32 * 32) return;
    int x = i & 31;
    int z = (i >> 5) & 31;
    int c = i >> 10;
    const float* p = feat + (((size_t)c * 32 + z) * 32) * 32 + x;
    float m = p[0];
#pragma unroll
    for (int y = 1; y < 32; y++) m = fmaxf(m, p[y * 32]);
    bev[i] = m;
}

// ---------------------------------------------------------------- bilinear resize 32x32 -> 200x200
// half-pixel centers, edge clamp (== jax.image.resize bilinear / torch align_corners=False)
__global__ void resize_kernel(const float* __restrict__ bev, float* __restrict__ out) {
    int i = blockIdx.x * blockDim.x + threadIdx.x;
    if (i >= 256 * 200 * 200) return;
    int ox = i % 200;
    int t  = i / 200;
    int oy = t % 200;
    int c  = t / 200;
    const float scale = 32.f / 200.f;
    float sy = (oy + 0.5f) * scale - 0.5f;
    float sx = (ox + 0.5f) * scale - 0.5f;
    int y0f = (int)floorf(sy); float fy = sy - (float)y0f;
    int x0f = (int)floorf(sx); float fx = sx - (float)x0f;
    int y0 = min(max(y0f, 0), 31), y1 = min(max(y0f + 1, 0), 31);
    int x0 = min(max(x0f, 0), 31), x1 = min(max(x0f + 1, 0), 31);
    const float* b = bev + (size_t)c * 1024;
    float v00 = b[y0 * 32 + x0], v01 = b[y0 * 32 + x1];
    float v10 = b[y1 * 32 + x0], v11 = b[y1 * 32 + x1];
    float v0 = v00 + (v01 - v00) * fx;
    float v1 = v10 + (v11 - v10) * fx;
    out[i] = v0 + (v1 - v0) * fy;
}

// ---------------------------------------------------------------- launch
extern "C" void kernel_launch(void* const* d_in, const int* in_sizes, int n_in,
                              void* d_out, int out_size) {
    const float* points = (const float*)d_in[0];
    const float* w[6]; const float* gm[6]; const float* bt[6];

    // Input ordering detection:
    //  interleaved (setup_inputs dict order): points, w1,g1,b1, w2,g2,b2, ...
    //    -> in_sizes[2]==in_sizes[3]==32 (g1,b1)
    //  grouped (reference signature order): points, w1..w6, g1..g6, b1..b6
    //    -> in_sizes[2]=55296 (w2) != in_sizes[3]=110592 (w3)
    if (n_in >= 4 && in_sizes[2] == in_sizes[3] && in_sizes[2] <= 1024) {
        for (int i = 0; i < 6; i++) {
            w[i]  = (const float*)d_in[1 + 3*i];
            gm[i] = (const float*)d_in[2 + 3*i];
            bt[i] = (const float*)d_in[3 + 3*i];
        }
    } else {
        for (int i = 0; i < 6; i++) {
            w[i]  = (const float*)d_in[1 + i];
            gm[i] = (const float*)d_in[7 + i];
            bt[i] = (const float*)d_in[13 + i];
        }
    }
    const int N = in_sizes[0] / 4;

    float *A, *B;
    cudaGetSymbolAddress((void**)&A, g_bufA);
    cudaGetSymbolAddress((void**)&B, g_bufB);

    // 1. zero voxel grid (4,128^3) in A, scatter points
    const int gridElems = 4 * G3;
    zero_kernel<<<(gridElems + 255) / 256, 256>>>(A, gridElems);
    voxelize_kernel<<<(N + 255) / 256, 256>>>((const float4*)points, A, N);

    // 2. conv stack (ping-pong A<->B)
    { dim3 gr(16 * 32 * 32,  2); conv_bn_relu_kernel<  4, 1><<<gr, 128>>>(A, w[0], gm[0], bt[0], B, 128, 128); }
    { dim3 gr( 8 * 16 * 16,  4); conv_bn_relu_kernel< 32, 2><<<gr, 128>>>(B, w[1], gm[1], bt[1], A, 128,  64); }
    { dim3 gr( 8 * 16 * 16,  4); conv_bn_relu_kernel< 64, 1><<<gr, 128>>>(A, w[2], gm[2], bt[2], B,  64,  64); }
    { dim3 gr( 4 *  8 *  8,  8); conv_bn_relu_kernel< 64, 2><<<gr, 128>>>(B, w[3], gm[3], bt[3], A,  64,  32); }
    { dim3 gr( 4 *  8 *  8,  8); conv_bn_relu_kernel<128, 1><<<gr, 128>>>(A, w[4], gm[4], bt[4], B,  32,  32); }
    { dim3 gr( 4 *  8 *  8, 16); conv_bn_relu_kernel<128, 1><<<gr, 128>>>(B, w[5], gm[5], bt[5], A,  32,  32); }

    // 3. BEV max over y: A (256,32,32,32) -> B (256,32,32)
    bevmax_kernel<<<(256 * 32 * 32 + 255) / 256, 256>>>(A, B);

    // 4. bilinear resize to (256,200,200)
    resize_kernel<<<(256 * 200 * 200 + 255) / 256, 256>>>(B, (float*)d_out);
}

// round 3
// speedup vs baseline: 1.2661x; 1.2661x over previous
#include <cuda_runtime.h>
#include <math.h>

#define G 128
#define G3 (G*G*G)

typedef unsigned long long ull;

// packed f32x2 helpers (sm_100+)
#define FMA2(d, a, b, c) \
    asm("fma.rn.f32x2 %0, %1, %2, %3;" : "=l"(d) : "l"(a), "l"(b), "l"(c))
#define PACK2(d, x) \
    asm("mov.b64 %0, {%1, %2};" : "=l"(d) : "r"(__float_as_uint(x)), "r"(__float_as_uint(x)))
#define UNPACK2(lo, hi, v) \
    asm("mov.b64 {%0, %1}, %2;" : "=f"(lo), "=f"(hi) : "l"(v))

// Ping-pong scratch (no cudaMalloc allowed).
__device__ float g_bufA[16777216];   // 67MB
__device__ float g_bufB[67108864];   // 268MB

// ---------------------------------------------------------------- utilities
__global__ void zero_kernel(float* __restrict__ p, int n) {
    int i = blockIdx.x * blockDim.x + threadIdx.x;
    if (i < n) p[i] = 0.f;
}

// ---------------------------------------------------------------- voxelize
__global__ void voxelize_kernel(const float4* __restrict__ pts, float* __restrict__ grid, int N) {
    int i = blockIdx.x * blockDim.x + threadIdx.x;
    if (i >= N) return;
    float4 p = pts[i];
    if (p.x < -32.f || p.x > 32.f ||
        p.y < -32.f || p.y > 32.f ||
        p.z < -32.f || p.z > 32.f) return;
    int cx = (int)floorf((p.x + 32.f) * 2.f);
    int cy = (int)floorf((p.y + 32.f) * 2.f);
    int cz = (int)floorf((p.z + 32.f) * 2.f);
    cx = cx < 0 ? 0 : (cx > G-1 ? G-1 : cx);
    cy = cy < 0 ? 0 : (cy > G-1 ? G-1 : cy);
    cz = cz < 0 ? 0 : (cz > G-1 ? G-1 : cz);
    int base = (cz * G + cy) * G + cx;
    atomicAdd(&grid[0*G3 + base], p.x);
    atomicAdd(&grid[1*G3 + base], p.y);
    atomicAdd(&grid[2*G3 + base], p.z);
    atomicAdd(&grid[3*G3 + base], p.w);
}

// ---------------------------------------------------------------- conv3d + BN + ReLU (f32x2)
// Block: 128 threads = (lz in [0,4), ly in [0,TY), lx in [0,TXT)).
// Each thread computes 8 consecutive x outputs (XPT=8) x 8 output channels.
// Output channels packed in f32x2 pairs; weights read as broadcast LDS.64.
template<int CI, int STRIDE, int TY, int TXT>
__global__ void __launch_bounds__(128, 4)
conv_f32x2_kernel(const float* __restrict__ in, const float* __restrict__ wgt,
                  const float* __restrict__ gamma, const float* __restrict__ beta,
                  float* __restrict__ out, int Sin, int Sout)
{
    constexpr int TZ = 4, XPT = 8;
    constexpr int TXO = TXT * XPT;                 // x outputs per block
    constexpr int HZ = (TZ - 1) * STRIDE + 3;
    constexpr int HY = (TY - 1) * STRIDE + 3;
    constexpr int HXO = (TXO - 1) * STRIDE + 3;
    constexpr int HTOT = HZ * HY * HXO;
    constexpr int RL = (XPT - 1) * STRIDE + 3;     // input row regs per thread: 10 (s1) / 17 (s2)

    __shared__ float s_in[HTOT];
    __shared__ __align__(16) float s_w[27 * 8];

    const int tid = threadIdx.x;
    const int lx = tid % TXT;
    const int ly = (tid / TXT) % TY;
    const int lz = tid / (TXT * TY);

    const int ntx = Sout / TXO, nty = Sout / TY;
    int bt = blockIdx.x;
    const int tx0 = (bt % ntx) * TXO; bt /= ntx;
    const int ty0 = (bt % nty) * TY;  bt /= nty;
    const int tz0 = bt * TZ;
    const int oc0 = blockIdx.y * 8;

    const int bz = tz0 * STRIDE - 1;
    const int by = ty0 * STRIDE - 1;
    const int bx = tx0 * STRIDE - 1;

    ull acc[XPT][4];
#pragma unroll
    for (int i = 0; i < XPT; i++)
#pragma unroll
        for (int p = 0; p < 4; p++) acc[i][p] = 0ULL;

    const int iz0 = lz * STRIDE, iy0 = ly * STRIDE;
    const int ixb = lx * XPT * STRIDE;

    for (int ci = 0; ci < CI; ci++) {
        const float* inc = in + (size_t)ci * Sin * Sin * Sin;
        // halo tile load (zero padded at volume borders)
        for (int idx = tid; idx < HTOT; idx += 128) {
            int iz = idx / (HY * HXO);
            int rem = idx - iz * (HY * HXO);
            int iy = rem / HXO;
            int ix = rem - iy * HXO;
            int gz = bz + iz, gy = by + iy, gx = bx + ix;
            float v = 0.f;
            if ((unsigned)gz < (unsigned)Sin && (unsigned)gy < (unsigned)Sin &&
                (unsigned)gx < (unsigned)Sin)
                v = inc[((size_t)gz * Sin + gy) * Sin + gx];
            s_in[idx] = v;
        }
        // weights: s_w[t*8 + oc] = wgt[((oc0+oc)*CI+ci)*27 + t]
        for (int idx = tid; idx < 216; idx += 128) {
            int t = idx >> 3, oc = idx & 7;
            s_w[idx] = wgt[((size_t)(oc0 + oc) * CI + ci) * 27 + t];
        }
        __syncthreads();

#pragma unroll
        for (int dz = 0; dz < 3; dz++) {
#pragma unroll
            for (int dy = 0; dy < 3; dy++) {
                const float* row = &s_in[((iz0 + dz) * HY + (iy0 + dy)) * HXO + ixb];
                if (STRIDE == 1) {
                    ull vv[10];
#pragma unroll
                    for (int j = 0; j < 10; j++) { float r = row[j]; PACK2(vv[j], r); }
#pragma unroll
                    for (int dx = 0; dx < 3; dx++) {
                        const ull* wp = (const ull*)&s_w[((dz * 3 + dy) * 3 + dx) * 8];
                        const ull w0 = wp[0], w1 = wp[1], w2 = wp[2], w3 = wp[3];
#pragma unroll
                        for (int xi = 0; xi < XPT; xi++) {
                            const ull v = vv[xi + dx];
                            FMA2(acc[xi][0], v, w0, acc[xi][0]);
                            FMA2(acc[xi][1], v, w1, acc[xi][1]);
                            FMA2(acc[xi][2], v, w2, acc[xi][2]);
                            FMA2(acc[xi][3], v, w3, acc[xi][3]);
                        }
                    }
                } else {
                    float r[RL];
#pragma unroll
                    for (int j = 0; j < RL; j++) r[j] = row[j];
#pragma unroll
                    for (int dx = 0; dx < 3; dx++) {
                        const ull* wp = (const ull*)&s_w[((dz * 3 + dy) * 3 + dx) * 8];
                        const ull w0 = wp[0], w1 = wp[1], w2 = wp[2], w3 = wp[3];
#pragma unroll
                        for (int xi = 0; xi < XPT; xi++) {
                            ull v; PACK2(v, r[xi * STRIDE + dx]);
                            FMA2(acc[xi][0], v, w0, acc[xi][0]);
                            FMA2(acc[xi][1], v, w1, acc[xi][1]);
                            FMA2(acc[xi][2], v, w2, acc[xi][2]);
                            FMA2(acc[xi][3], v, w3, acc[xi][3]);
                        }
                    }
                }
            }
        }
        __syncthreads();
    }

    // epilogue: BN (mean 0, var 1) + ReLU, vectorized stores
    const int oz = tz0 + lz, oy = ty0 + ly, ox0 = tx0 + lx * XPT;
    const float inv = rsqrtf(1.f + 1e-5f);
    const size_t S3 = (size_t)Sout * Sout * Sout;
    const size_t sp = ((size_t)oz * Sout + oy) * Sout + ox0;
#pragma unroll
    for (int p = 0; p < 4; p++) {
        const int ocA = oc0 + 2 * p, ocB = ocA + 1;
        const float sA = gamma[ocA] * inv, bA = beta[ocA];
        const float sB = gamma[ocB] * inv, bB = beta[ocB];
        float lo[XPT], hi[XPT];
#pragma unroll
        for (int xi = 0; xi < XPT; xi++) {
            UNPACK2(lo[xi], hi[xi], acc[xi][p]);
            lo[xi] = fmaxf(lo[xi] * sA + bA, 0.f);
            hi[xi] = fmaxf(hi[xi] * sB + bB, 0.f);
        }
        float4* dA = (float4*)(out + (size_t)ocA * S3 + sp);
        float4* dB = (float4*)(out + (size_t)ocB * S3 + sp);
        dA[0] = make_float4(lo[0], lo[1], lo[2], lo[3]);
        dA[1] = make_float4(lo[4], lo[5], lo[6], lo[7]);
        dB[0] = make_float4(hi[0], hi[1], hi[2], hi[3]);
        dB[1] = make_float4(hi[4], hi[5], hi[6], hi[7]);
    }
}

// ---------------------------------------------------------------- BEV max over H (y)
__global__ void bevmax_kernel(const float* __restrict__ feat, float* __restrict__ bev) {
    int i = blockIdx.x * blockDim.x + threadIdx.x;
    if (i >= 256 * 32 * 32) return;
    int x = i & 31;
    int z = (i >> 5) & 31;
    int c = i >> 10;
    const float* p = feat + (((size_t)c * 32 + z) * 32) * 32 + x;
    float m = p[0];
#pragma unroll
    for (int y = 1; y < 32; y++) m = fmaxf(m, p[y * 32]);
    bev[i] = m;
}

// ---------------------------------------------------------------- bilinear resize 32x32 -> 200x200
__global__ void resize_kernel(const float* __restrict__ bev, float* __restrict__ out) {
    int i = blockIdx.x * blockDim.x + threadIdx.x;
    if (i >= 256 * 200 * 200) return;
    int ox = i % 200;
    int t  = i / 200;
    int oy = t % 200;
    int c  = t / 200;
    const float scale = 32.f / 200.f;
    float sy = (oy + 0.5f) * scale - 0.5f;
    float sx = (ox + 0.5f) * scale - 0.5f;
    int y0f = (int)floorf(sy); float fy = sy - (float)y0f;
    int x0f = (int)floorf(sx); float fx = sx - (float)x0f;
    int y0 = min(max(y0f, 0), 31), y1 = min(max(y0f + 1, 0), 31);
    int x0 = min(max(x0f, 0), 31), x1 = min(max(x0f + 1, 0), 31);
    const float* b = bev + (size_t)c * 1024;
    float v00 = b[y0 * 32 + x0], v01 = b[y0 * 32 + x1];
    float v10 = b[y1 * 32 + x0], v11 = b[y1 * 32 + x1];
    float v0 = v00 + (v01 - v00) * fx;
    float v1 = v10 + (v11 - v10) * fx;
    out[i] = v0 + (v1 - v0) * fy;
}

// ---------------------------------------------------------------- launch
extern "C" void kernel_launch(void* const* d_in, const int* in_sizes, int n_in,
                              void* d_out, int out_size) {
    const float* points = (const float*)d_in[0];
    const float* w[6]; const float* gm[6]; const float* bt[6];

    // interleaved (points, w1,g1,b1, ...) vs grouped (points, w1..w6, g1..g6, b1..b6)
    if (n_in >= 4 && in_sizes[2] == in_sizes[3] && in_sizes[2] <= 1024) {
        for (int i = 0; i < 6; i++) {
            w[i]  = (const float*)d_in[1 + 3*i];
            gm[i] = (const float*)d_in[2 + 3*i];
            bt[i] = (const float*)d_in[3 + 3*i];
        }
    } else {
        for (int i = 0; i < 6; i++) {
            w[i]  = (const float*)d_in[1 + i];
            gm[i] = (const float*)d_in[7 + i];
            bt[i] = (const float*)d_in[13 + i];
        }
    }
    const int N = in_sizes[0] / 4;

    float *A, *B;
    cudaGetSymbolAddress((void**)&A, g_bufA);
    cudaGetSymbolAddress((void**)&B, g_bufB);

    // 1. voxelize into A (4,128^3)
    const int gridElems = 4 * G3;
    zero_kernel<<<(gridElems + 255) / 256, 256>>>(A, gridElems);
    voxelize_kernel<<<(N + 255) / 256, 256>>>((const float4*)points, A, N);

    // 2. conv stack (ping-pong A<->B)
    // L1: 4->32,  s1, 128^3: tile 4x4x64 (TY=4,TXT=8): ntx=2,nty=32,ntz=32
    { dim3 gr(2 * 32 * 32,  4); conv_f32x2_kernel<  4, 1, 4, 8><<<gr, 128>>>(A, w[0], gm[0], bt[0], B, 128, 128); }
    // L2: 32->64, s2, ->64^3: ntx=1,nty=16,ntz=16
    { dim3 gr(1 * 16 * 16,  8); conv_f32x2_kernel< 32, 2, 4, 8><<<gr, 128>>>(B, w[1], gm[1], bt[1], A, 128,  64); }
    // L3: 64->64, s1, 64^3
    { dim3 gr(1 * 16 * 16,  8); conv_f32x2_kernel< 64, 1, 4, 8><<<gr, 128>>>(A, w[2], gm[2], bt[2], B,  64,  64); }
    // L4: 64->128, s2, ->32^3: tile 4x8x32 (TY=8,TXT=4): ntx=1,nty=4,ntz=8
    { dim3 gr(1 *  4 *  8, 16); conv_f32x2_kernel< 64, 2, 8, 4><<<gr, 128>>>(B, w[3], gm[3], bt[3], A,  64,  32); }
    // L5: 128->128, s1, 32^3
    { dim3 gr(1 *  4 *  8, 16); conv_f32x2_kernel<128, 1, 8, 4><<<gr, 128>>>(A, w[4], gm[4], bt[4], B,  32,  32); }
    // L6: 128->256, s1, 32^3
    { dim3 gr(1 *  4 *  8, 32); conv_f32x2_kernel<128, 1, 8, 4><<<gr, 128>>>(B, w[5], gm[5], bt[5], A,  32,  32); }

    // 3. BEV max over y: A (256,32,32,32) -> B (256,32,32)
    bevmax_kernel<<<(256 * 32 * 32 + 255) / 256, 256>>>(A, B);

    // 4. bilinear resize to (256,200,200)
    resize_kernel<<<(256 * 200 * 200 + 255) / 256, 256>>>(B, (float*)d_out);
}

// round 4
// speedup vs baseline: 1.4824x; 1.1708x over previous
#include <cuda_runtime.h>
#include <math.h>

#define G 128
#define G3 (G*G*G)

typedef unsigned long long ull;

// packed f32x2 helpers (sm_100+)
#define FMA2(d, a, b, c) \
    asm("fma.rn.f32x2 %0, %1, %2, %3;" : "=l"(d) : "l"(a), "l"(b), "l"(c))
#define PACK2(d, x) \
    asm("mov.b64 %0, {%1, %2};" : "=l"(d) : "r"(__float_as_uint(x)), "r"(__float_as_uint(x)))
#define UNPACK2(lo, hi, v) \
    asm("mov.b64 {%0, %1}, %2;" : "=f"(lo), "=f"(hi) : "l"(v))

__device__ __forceinline__ void cp4(unsigned dst, const float* src, unsigned sz) {
    asm volatile("cp.async.ca.shared.global [%0], [%1], 4, %2;" :: "r"(dst), "l"(src), "r"(sz));
}
__device__ __forceinline__ void cp_commit() { asm volatile("cp.async.commit_group;"); }
__device__ __forceinline__ void cp_wait0() { asm volatile("cp.async.wait_group 0;"); }

// Ping-pong scratch (no cudaMalloc allowed).
__device__ float g_bufA[16777216];   // 67MB
__device__ float g_bufB[67108864];   // 268MB

// ---------------------------------------------------------------- utilities
__global__ void zero_kernel(float* __restrict__ p, int n) {
    int i = blockIdx.x * blockDim.x + threadIdx.x;
    if (i < n) p[i] = 0.f;
}

// ---------------------------------------------------------------- voxelize
__global__ void voxelize_kernel(const float4* __restrict__ pts, float* __restrict__ grid, int N) {
    int i = blockIdx.x * blockDim.x + threadIdx.x;
    if (i >= N) return;
    float4 p = pts[i];
    if (p.x < -32.f || p.x > 32.f ||
        p.y < -32.f || p.y > 32.f ||
        p.z < -32.f || p.z > 32.f) return;
    int cx = (int)floorf((p.x + 32.f) * 2.f);
    int cy = (int)floorf((p.y + 32.f) * 2.f);
    int cz = (int)floorf((p.z + 32.f) * 2.f);
    cx = cx < 0 ? 0 : (cx > G-1 ? G-1 : cx);
    cy = cy < 0 ? 0 : (cy > G-1 ? G-1 : cy);
    cz = cz < 0 ? 0 : (cz > G-1 ? G-1 : cz);
    int base = (cz * G + cy) * G + cx;
    atomicAdd(&grid[0*G3 + base], p.x);
    atomicAdd(&grid[1*G3 + base], p.y);
    atomicAdd(&grid[2*G3 + base], p.z);
    atomicAdd(&grid[3*G3 + base], p.w);
}

// ---------------------------------------------------------------- stride-1 conv + BN + ReLU
// Double-buffered cp.async over ci, precomputed halo offset table in smem.
// 128 threads = TZ(4) x TY x TXT; each thread: 8 x-outputs x 8 output channels
// (4 f32x2 channel-pair accumulators per x).
template<int CI, int TY, int TXT>
__global__ void __launch_bounds__(128, 4)
conv_s1_db_kernel(const float* __restrict__ in, const float* __restrict__ wgt,
                  const float* __restrict__ gamma, const float* __restrict__ beta,
                  float* __restrict__ out, int Sin, int Sout)
{
    constexpr int TZ = 4, XPT = 8;
    constexpr int TXO = TXT * XPT;
    constexpr int HZ = TZ + 2, HY = TY + 2, HXO = TXO + 2;
    constexpr int HTOT = HZ * HY * HXO;
    constexpr int ITERS = (HTOT + 127) / 128;

    __shared__ int s_off[HTOT];
    __shared__ float s_in[2][HTOT];
    __shared__ __align__(16) float s_w[2][216];

    const int tid = threadIdx.x;
    const int lx = tid % TXT;
    const int ly = (tid / TXT) % TY;
    const int lz = tid / (TXT * TY);

    const int ntx = Sout / TXO, nty = Sout / TY;
    int bt = blockIdx.x;
    const int tx0 = (bt % ntx) * TXO; bt /= ntx;
    const int ty0 = (bt % nty) * TY;  bt /= nty;
    const int tz0 = bt * TZ;
    const int oc0 = blockIdx.y * 8;

    const int bz = tz0 - 1, by = ty0 - 1, bx = tx0 - 1;

    // ---- build halo offset table (once per block)
    for (int idx = tid; idx < HTOT; idx += 128) {
        int iz = idx / (HY * HXO);
        int rem = idx - iz * (HY * HXO);
        int iy = rem / HXO;
        int ix = rem - iy * HXO;
        int gz = bz + iz, gy = by + iy, gx = bx + ix;
        int off = -1;
        if ((unsigned)gz < (unsigned)Sin && (unsigned)gy < (unsigned)Sin &&
            (unsigned)gx < (unsigned)Sin)
            off = (gz * Sin + gy) * Sin + gx;
        s_off[idx] = off;
    }

    // ---- weight pointers: s_w layout [t*8+oc], two slots per thread
    const float* wp0 = nullptr; const float* wp1 = nullptr;
    {
        int i0 = tid;            // < 216 always (tid<128)
        int t0 = i0 >> 3, o0 = i0 & 7;
        wp0 = wgt + ((size_t)(oc0 + o0) * CI) * 27 + t0;
        int i1 = tid + 128;
        if (i1 < 216) {
            int t1 = i1 >> 3, o1 = i1 & 7;
            wp1 = wgt + ((size_t)(oc0 + o1) * CI) * 27 + t1;
        }
    }
    __syncthreads();

    const size_t Sin3 = (size_t)Sin * Sin * Sin;

    unsigned sin_base = (unsigned)__cvta_generic_to_shared(&s_in[0][0]);
    unsigned sw_base  = (unsigned)__cvta_generic_to_shared(&s_w[0][0]);

    // prefetch ci = 0 into buffer 0
    {
        const float* inc = in;
#pragma unroll
        for (int k = 0; k < ITERS; k++) {
            int idx = tid + k * 128;
            if (idx < HTOT) {
                int o = s_off[idx];
                cp4(sin_base + idx * 4, inc + (o >= 0 ? o : 0), o >= 0 ? 4u : 0u);
            }
        }
        cp4(sw_base + tid * 4, wp0, 4u);
        if (wp1) cp4(sw_base + (tid + 128) * 4, wp1, 4u);
        cp_commit();
    }

    ull acc[XPT][4];
#pragma unroll
    for (int i = 0; i < XPT; i++)
#pragma unroll
        for (int p = 0; p < 4; p++) acc[i][p] = 0ULL;

    const int iz0 = lz, iy0 = ly, ixb = lx * XPT;

    for (int ci = 0; ci < CI; ci++) {
        cp_wait0();
        __syncthreads();

        const int cur = ci & 1, nxt = cur ^ 1;
        // prefetch ci+1 into the other buffer (overlaps with compute below)
        if (ci + 1 < CI) {
            const float* inc = in + (size_t)(ci + 1) * Sin3;
            unsigned dstb = sin_base + nxt * (HTOT * 4);
#pragma unroll
            for (int k = 0; k < ITERS; k++) {
                int idx = tid + k * 128;
                if (idx < HTOT) {
                    int o = s_off[idx];
                    cp4(dstb + idx * 4, inc + (o >= 0 ? o : 0), o >= 0 ? 4u : 0u);
                }
            }
            unsigned dw = sw_base + nxt * (216 * 4);
            cp4(dw + tid * 4, wp0 + (ci + 1) * 27, 4u);
            if (wp1) cp4(dw + (tid + 128) * 4, wp1 + (ci + 1) * 27, 4u);
            cp_commit();
        } else {
            cp_commit();  // keep group count consistent
        }

        const float* sbuf = &s_in[cur][0];
        const float* swb  = &s_w[cur][0];

#pragma unroll
        for (int dz = 0; dz < 3; dz++) {
#pragma unroll
            for (int dy = 0; dy < 3; dy++) {
                const float* row = &sbuf[((iz0 + dz) * HY + (iy0 + dy)) * HXO + ixb];
                ull vv[10];
#pragma unroll
                for (int j = 0; j < 10; j++) { float r = row[j]; PACK2(vv[j], r); }
#pragma unroll
                for (int dx = 0; dx < 3; dx++) {
                    const ull* wp = (const ull*)&swb[((dz * 3 + dy) * 3 + dx) * 8];
                    const ull w0 = wp[0], w1 = wp[1], w2 = wp[2], w3 = wp[3];
#pragma unroll
                    for (int xi = 0; xi < XPT; xi++) {
                        const ull v = vv[xi + dx];
                        FMA2(acc[xi][0], v, w0, acc[xi][0]);
                        FMA2(acc[xi][1], v, w1, acc[xi][1]);
                        FMA2(acc[xi][2], v, w2, acc[xi][2]);
                        FMA2(acc[xi][3], v, w3, acc[xi][3]);
                    }
                }
            }
        }
        __syncthreads();
    }

    // epilogue: BN (mean 0, var 1) + ReLU
    const int oz = tz0 + lz, oy = ty0 + ly, ox0 = tx0 + lx * XPT;
    const float inv = rsqrtf(1.f + 1e-5f);
    const size_t S3 = (size_t)Sout * Sout * Sout;
    const size_t sp = ((size_t)oz * Sout + oy) * Sout + ox0;
#pragma unroll
    for (int p = 0; p < 4; p++) {
        const int ocA = oc0 + 2 * p, ocB = ocA + 1;
        const float sA = gamma[ocA] * inv, bA = beta[ocA];
        const float sB = gamma[ocB] * inv, bB = beta[ocB];
        float lo[XPT], hi[XPT];
#pragma unroll
        for (int xi = 0; xi < XPT; xi++) {
            UNPACK2(lo[xi], hi[xi], acc[xi][p]);
            lo[xi] = fmaxf(lo[xi] * sA + bA, 0.f);
            hi[xi] = fmaxf(hi[xi] * sB + bB, 0.f);
        }
        float4* dA = (float4*)(out + (size_t)ocA * S3 + sp);
        float4* dB = (float4*)(out + (size_t)ocB * S3 + sp);
        dA[0] = make_float4(lo[0], lo[1], lo[2], lo[3]);
        dA[1] = make_float4(lo[4], lo[5], lo[6], lo[7]);
        dB[0] = make_float4(hi[0], hi[1], hi[2], hi[3]);
        dB[1] = make_float4(hi[4], hi[5], hi[6], hi[7]);
    }
}

// ---------------------------------------------------------------- stride-2 conv (R3 kernel)
template<int CI, int STRIDE, int TY, int TXT>
__global__ void __launch_bounds__(128, 4)
conv_f32x2_kernel(const float* __restrict__ in, const float* __restrict__ wgt,
                  const float* __restrict__ gamma, const float* __restrict__ beta,
                  float* __restrict__ out, int Sin, int Sout)
{
    constexpr int TZ = 4, XPT = 8;
    constexpr int TXO = TXT * XPT;
    constexpr int HZ = (TZ - 1) * STRIDE + 3;
    constexpr int HY = (TY - 1) * STRIDE + 3;
    constexpr int HXO = (TXO - 1) * STRIDE + 3;
    constexpr int HTOT = HZ * HY * HXO;
    constexpr int RL = (XPT - 1) * STRIDE + 3;

    __shared__ float s_in[HTOT];
    __shared__ __align__(16) float s_w[27 * 8];

    const int tid = threadIdx.x;
    const int lx = tid % TXT;
    const int ly = (tid / TXT) % TY;
    const int lz = tid / (TXT * TY);

    const int ntx = Sout / TXO, nty = Sout / TY;
    int bt = blockIdx.x;
    const int tx0 = (bt % ntx) * TXO; bt /= ntx;
    const int ty0 = (bt % nty) * TY;  bt /= nty;
    const int tz0 = bt * TZ;
    const int oc0 = blockIdx.y * 8;

    const int bz = tz0 * STRIDE - 1;
    const int by = ty0 * STRIDE - 1;
    const int bx = tx0 * STRIDE - 1;

    ull acc[XPT][4];
#pragma unroll
    for (int i = 0; i < XPT; i++)
#pragma unroll
        for (int p = 0; p < 4; p++) acc[i][p] = 0ULL;

    const int iz0 = lz * STRIDE, iy0 = ly * STRIDE;
    const int ixb = lx * XPT * STRIDE;

    for (int ci = 0; ci < CI; ci++) {
        const float* inc = in + (size_t)ci * Sin * Sin * Sin;
        for (int idx = tid; idx < HTOT; idx += 128) {
            int iz = idx / (HY * HXO);
            int rem = idx - iz * (HY * HXO);
            int iy = rem / HXO;
            int ix = rem - iy * HXO;
            int gz = bz + iz, gy = by + iy, gx = bx + ix;
            float v = 0.f;
            if ((unsigned)gz < (unsigned)Sin && (unsigned)gy < (unsigned)Sin &&
                (unsigned)gx < (unsigned)Sin)
                v = inc[((size_t)gz * Sin + gy) * Sin + gx];
            s_in[idx] = v;
        }
        for (int idx = tid; idx < 216; idx += 128) {
            int t = idx >> 3, oc = idx & 7;
            s_w[idx] = wgt[((size_t)(oc0 + oc) * CI + ci) * 27 + t];
        }
        __syncthreads();

#pragma unroll
        for (int dz = 0; dz < 3; dz++) {
#pragma unroll
            for (int dy = 0; dy < 3; dy++) {
                const float* row = &s_in[((iz0 + dz) * HY + (iy0 + dy)) * HXO + ixb];
                ull vv[RL];
#pragma unroll
                for (int j = 0; j < RL; j++) { float r = row[j]; PACK2(vv[j], r); }
#pragma unroll
                for (int dx = 0; dx < 3; dx++) {
                    const ull* wp = (const ull*)&s_w[((dz * 3 + dy) * 3 + dx) * 8];
                    const ull w0 = wp[0], w1 = wp[1], w2 = wp[2], w3 = wp[3];
#pragma unroll
                    for (int xi = 0; xi < XPT; xi++) {
                        const ull v = vv[xi * STRIDE + dx];
                        FMA2(acc[xi][0], v, w0, acc[xi][0]);
                        FMA2(acc[xi][1], v, w1, acc[xi][1]);
                        FMA2(acc[xi][2], v, w2, acc[xi][2]);
                        FMA2(acc[xi][3], v, w3, acc[xi][3]);
                    }
                }
            }
        }
        __syncthreads();
    }

    const int oz = tz0 + lz, oy = ty0 + ly, ox0 = tx0 + lx * XPT;
    const float inv = rsqrtf(1.f + 1e-5f);
    const size_t S3 = (size_t)Sout * Sout * Sout;
    const size_t sp = ((size_t)oz * Sout + oy) * Sout + ox0;
#pragma unroll
    for (int p = 0; p < 4; p++) {
        const int ocA = oc0 + 2 * p, ocB = ocA + 1;
        const float sA = gamma[ocA] * inv, bA = beta[ocA];
        const float sB = gamma[ocB] * inv, bB = beta[ocB];
        float lo[XPT], hi[XPT];
#pragma unroll
        for (int xi = 0; xi < XPT; xi++) {
            UNPACK2(lo[xi], hi[xi], acc[xi][p]);
            lo[xi] = fmaxf(lo[xi] * sA + bA, 0.f);
            hi[xi] = fmaxf(hi[xi] * sB + bB, 0.f);
        }
        float4* dA = (float4*)(out + (size_t)ocA * S3 + sp);
        float4* dB = (float4*)(out + (size_t)ocB * S3 + sp);
        dA[0] = make_float4(lo[0], lo[1], lo[2], lo[3]);
        dA[1] = make_float4(lo[4], lo[5], lo[6], lo[7]);
        dB[0] = make_float4(hi[0], hi[1], hi[2], hi[3]);
        dB[1] = make_float4(hi[4], hi[5], hi[6], hi[7]);
    }
}

// ---------------------------------------------------------------- BEV max over H (y)
__global__ void bevmax_kernel(const float* __restrict__ feat, float* __restrict__ bev) {
    int i = blockIdx.x * blockDim.x + threadIdx.x;
    if (i >= 256 * 32 * 32) return;
    int x = i & 31;
    int z = (i >> 5) & 31;
    int c = i >> 10;
    const float* p = feat + (((size_t)c * 32 + z) * 32) * 32 + x;
    float m = p[0];
#pragma unroll
    for (int y = 1; y < 32; y++) m = fmaxf(m, p[y * 32]);
    bev[i] = m;
}

// ---------------------------------------------------------------- bilinear resize 32x32 -> 200x200
__global__ void resize_kernel(const float* __restrict__ bev, float* __restrict__ out) {
    int i = blockIdx.x * blockDim.x + threadIdx.x;
    if (i >= 256 * 200 * 200) return;
    int ox = i % 200;
    int t  = i / 200;
    int oy = t % 200;
    int c  = t / 200;
    const float scale = 32.f / 200.f;
    float sy = (oy + 0.5f) * scale - 0.5f;
    float sx = (ox + 0.5f) * scale - 0.5f;
    int y0f = (int)floorf(sy); float fy = sy - (float)y0f;
    int x0f = (int)floorf(sx); float fx = sx - (float)x0f;
    int y0 = min(max(y0f, 0), 31), y1 = min(max(y0f + 1, 0), 31);
    int x0 = min(max(x0f, 0), 31), x1 = min(max(x0f + 1, 0), 31);
    const float* b = bev + (size_t)c * 1024;
    float v00 = b[y0 * 32 + x0], v01 = b[y0 * 32 + x1];
    float v10 = b[y1 * 32 + x0], v11 = b[y1 * 32 + x1];
    float v0 = v00 + (v01 - v00) * fx;
    float v1 = v10 + (v11 - v10) * fx;
    out[i] = v0 + (v1 - v0) * fy;
}

// ---------------------------------------------------------------- launch
extern "C" void kernel_launch(void* const* d_in, const int* in_sizes, int n_in,
                              void* d_out, int out_size) {
    const float* points = (const float*)d_in[0];
    const float* w[6]; const float* gm[6]; const float* bt[6];

    // interleaved (points, w1,g1,b1, ...) vs grouped (points, w1..w6, g1..g6, b1..b6)
    if (n_in >= 4 && in_sizes[2] == in_sizes[3] && in_sizes[2] <= 1024) {
        for (int i = 0; i < 6; i++) {
            w[i]  = (const float*)d_in[1 + 3*i];
            gm[i] = (const float*)d_in[2 + 3*i];
            bt[i] = (const float*)d_in[3 + 3*i];
        }
    } else {
        for (int i = 0; i < 6; i++) {
            w[i]  = (const float*)d_in[1 + i];
            gm[i] = (const float*)d_in[7 + i];
            bt[i] = (const float*)d_in[13 + i];
        }
    }
    const int N = in_sizes[0] / 4;

    float *A, *B;
    cudaGetSymbolAddress((void**)&A, g_bufA);
    cudaGetSymbolAddress((void**)&B, g_bufB);

    // 1. voxelize into A (4,128^3)
    const int gridElems = 4 * G3;
    zero_kernel<<<(gridElems + 255) / 256, 256>>>(A, gridElems);
    voxelize_kernel<<<(N + 255) / 256, 256>>>((const float4*)points, A, N);

    // 2. conv stack (ping-pong A<->B)
    // L1: 4->32,  s1, 128^3  (tile 4z x 4y x 64x)
    { dim3 gr(2 * 32 * 32,  4); conv_s1_db_kernel<  4, 4, 8><<<gr, 128>>>(A, w[0], gm[0], bt[0], B, 128, 128); }
    // L2: 32->64, s2, ->64^3
    { dim3 gr(1 * 16 * 16,  8); conv_f32x2_kernel< 32, 2, 4, 8><<<gr, 128>>>(B, w[1], gm[1], bt[1], A, 128,  64); }
    // L3: 64->64, s1, 64^3
    { dim3 gr(1 * 16 * 16,  8); conv_s1_db_kernel< 64, 4, 8><<<gr, 128>>>(A, w[2], gm[2], bt[2], B,  64,  64); }
    // L4: 64->128, s2, ->32^3 (tile 4z x 8y x 32x)
    { dim3 gr(1 *  4 *  8, 16); conv_f32x2_kernel< 64, 2, 8, 4><<<gr, 128>>>(B, w[3], gm[3], bt[3], A,  64,  32); }
    // L5: 128->128, s1, 32^3
    { dim3 gr(1 *  4 *  8, 16); conv_s1_db_kernel<128, 8, 4><<<gr, 128>>>(A, w[4], gm[4], bt[4], B,  32,  32); }
    // L6: 128->256, s1, 32^3
    { dim3 gr(1 *  4 *  8, 32); conv_s1_db_kernel<128, 8, 4><<<gr, 128>>>(B, w[5], gm[5], bt[5], A,  32,  32); }

    // 3. BEV max over y: A (256,32,32,32) -> B (256,32,32)
    bevmax_kernel<<<(256 * 32 * 32 + 255) / 256, 256>>>(A, B);

    // 4. bilinear resize to (256,200,200)
    resize_kernel<<<(256 * 200 * 200 + 255) / 256, 256>>>(B, (float*)d_out);
}

// round 6
// speedup vs baseline: 3.4985x; 2.3601x over previous
#include <cuda_runtime.h>
#include <cuda_fp16.h>
#include <math.h>
#include <stdint.h>

#define G 128
#define G3 (G*G*G)

typedef unsigned long long ull;

// ---------------- packed f32x2 helpers (fp32 L1 kernel) ----------------
#define FMA2(d, a, b, c) \
    asm("fma.rn.f32x2 %0, %1, %2, %3;" : "=l"(d) : "l"(a), "l"(b), "l"(c))
#define PACK2(d, x) \
    asm("mov.b64 %0, {%1, %2};" : "=l"(d) : "r"(__float_as_uint(x)), "r"(__float_as_uint(x)))
#define UNPACK2(lo, hi, v) \
    asm("mov.b64 {%0, %1}, %2;" : "=f"(lo), "=f"(hi) : "l"(v))

__device__ __forceinline__ void cp4(unsigned dst, const float* src, unsigned sz) {
    asm volatile("cp.async.ca.shared.global [%0], [%1], 4, %2;" :: "r"(dst), "l"(src), "r"(sz));
}
__device__ __forceinline__ void cp16(unsigned dst, const void* src) {
    asm volatile("cp.async.cg.shared.global [%0], [%1], 16;" :: "r"(dst), "l"(src));
}
__device__ __forceinline__ void cp_commit() { asm volatile("cp.async.commit_group;"); }
__device__ __forceinline__ void cp_wait0() { asm volatile("cp.async.wait_group 0;"); }

// m16n8k16 fp16 MMA, f32 accumulate (base sm_80+ instruction — no 'a' feature)
#define MMA16816(d, a, b) \
    asm volatile("mma.sync.aligned.m16n8k16.row.col.f32.f16.f16.f32 " \
        "{%0,%1,%2,%3}, {%4,%5,%6,%7}, {%8,%9}, {%0,%1,%2,%3};" \
        : "+f"((d)[0]), "+f"((d)[1]), "+f"((d)[2]), "+f"((d)[3]) \
        : "r"((a)[0]), "r"((a)[1]), "r"((a)[2]), "r"((a)[3]), \
          "r"((b)[0]), "r"((b)[1]))

__device__ __forceinline__ uint32_t packh2(float a, float b) {
    __half2 h = __floats2half2_rn(a, b);
    return *(uint32_t*)&h;
}

// ---------------- scratch buffers ----------------
__device__ float g_bufA[16777216];     // 67MB
__device__ float g_bufB[67108864];     // 268MB
__device__ __half g_bufW[4063232];     // 8.1MB split fp16 weights

// ---------------------------------------------------------------- utilities
__global__ void zero_kernel(float* __restrict__ p, int n) {
    int i = blockIdx.x * blockDim.x + threadIdx.x;
    if (i < n) p[i] = 0.f;
}

// ---------------------------------------------------------------- voxelize
__global__ void voxelize_kernel(const float4* __restrict__ pts, float* __restrict__ grid, int N) {
    int i = blockIdx.x * blockDim.x + threadIdx.x;
    if (i >= N) return;
    float4 p = pts[i];
    if (p.x < -32.f || p.x > 32.f ||
        p.y < -32.f || p.y > 32.f ||
        p.z < -32.f || p.z > 32.f) return;
    int cx = (int)floorf((p.x + 32.f) * 2.f);
    int cy = (int)floorf((p.y + 32.f) * 2.f);
    int cz = (int)floorf((p.z + 32.f) * 2.f);
    cx = cx < 0 ? 0 : (cx > G-1 ? G-1 : cx);
    cy = cy < 0 ? 0 : (cy > G-1 ? G-1 : cy);
    cz = cz < 0 ? 0 : (cz > G-1 ? G-1 : cz);
    int base = (cz * G + cy) * G + cx;
    atomicAdd(&grid[0*G3 + base], p.x);
    atomicAdd(&grid[1*G3 + base], p.y);
    atomicAdd(&grid[2*G3 + base], p.z);
    atomicAdd(&grid[3*G3 + base], p.w);
}

// ---------------------------------------------------------------- weight prep (hi/lo fp16)
// dst[(ci*CO+co)*64]: halves 0..31 = fp16_hi(w taps 0..26, pad 0), 32..63 = fp16_lo
__global__ void prep_w_kernel(const float* __restrict__ w, __half* __restrict__ dst,
                              int CI, int CO) {
    int i = blockIdx.x * blockDim.x + threadIdx.x;
    if (i >= CI * CO) return;
    int ci = i / CO, co = i - ci * CO;
    const float* ws = w + ((size_t)co * CI + ci) * 27;
    __half* o = dst + (size_t)i * 64;
#pragma unroll
    for (int t = 0; t < 27; t++) {
        float a = ws[t];
        __half h = __float2half_rn(a);
        o[t] = h;
        o[32 + t] = __float2half_rn(a - __half2float(h));
    }
#pragma unroll
    for (int t = 27; t < 32; t++) { o[t] = __ushort_as_half(0); o[32 + t] = __ushort_as_half(0); }
}

// ---------------------------------------------------------------- mma.sync implicit-GEMM conv
// D[m,n] = sum_k A[m,k] B[n,k]; m = 128 voxels/block, n = 64 channels/block, k = 32/ci (27 taps).
// fp16 hi/lo split, 3 products: AhBh + AlBh + AhBl.
template<int CI, int STRIDE>
__global__ void __launch_bounds__(128)
conv_mma_kernel(const float* __restrict__ in, const __half* __restrict__ Wp,
                const float* __restrict__ gamma, const float* __restrict__ beta,
                float* __restrict__ out, int Sin, int Sout, int CO)
{
    constexpr int PA = 40;   // half pitch (80B, 16B aligned, conflict-free frags)
    constexpr int PB = 40;
    __shared__ __align__(16) char smem_raw[33792];
    __half* sAh = (__half*)smem_raw;            // 128*40 halves = 10240B
    __half* sAl = sAh + 128 * PA;               // 10240B
    __half* sBh = sAl + 128 * PA;               // 64*40 = 5120B
    __half* sBl = sBh + 64 * PB;                // 5120B  (total 30720B)
    float* sT = (float*)smem_raw;               // epilogue: 64 x 132 floats = 33792B

    const int tid = threadIdx.x;
    const int w = tid >> 5, lane = tid & 31;
    const int g = lane >> 2, tg = lane & 3;

    const int vbase = blockIdx.x * 128;
    const int oc0 = blockIdx.y * 64;
    const int v = vbase + tid;
    const int gx = v % Sout;
    const int t1 = v / Sout;
    const int gy = t1 % Sout;
    const int gz = t1 / Sout;
    const int jx = gx * STRIDE, jy = gy * STRIDE, jz = gz * STRIDE;
    const size_t SinSq = (size_t)Sin * Sin, Sin3 = SinSq * Sin;

    const uint32_t sb_h = (uint32_t)__cvta_generic_to_shared(sBh);
    const uint32_t sb_l = (uint32_t)__cvta_generic_to_shared(sBl);

    float acc[2][8][4];
#pragma unroll
    for (int mt = 0; mt < 2; mt++)
#pragma unroll
        for (int nt = 0; nt < 8; nt++)
#pragma unroll
            for (int q = 0; q < 4; q++) acc[mt][nt][q] = 0.f;

    for (int ci = 0; ci < CI; ci++) {
        // ---- stage B via cp.async: 64 rows x 8 x 16B
        {
            const char* srcb = (const char*)(Wp + ((size_t)ci * CO + oc0) * 64);
            for (int u = tid; u < 512; u += 128) {
                int co = u >> 3, seg = u & 7;
                uint32_t d = (seg < 4) ? (sb_h + (co * PB + seg * 8) * 2)
                                       : (sb_l + (co * PB + (seg - 4) * 8) * 2);
                cp16(d, srcb + co * 128 + seg * 16);
            }
            cp_commit();
        }
        // ---- gather 27 taps (coalesced along x), split hi/lo, write A row
        {
            float vv[27];
#pragma unroll
            for (int dz = 0; dz < 3; dz++) {
                int iz = jz + dz - 1;
                bool zv = (unsigned)iz < (unsigned)Sin;
#pragma unroll
                for (int dy = 0; dy < 3; dy++) {
                    int iy = jy + dy - 1;
                    bool yv = zv && ((unsigned)iy < (unsigned)Sin);
                    const float* p = in + (size_t)ci * Sin3 + (size_t)iz * SinSq
                                        + (size_t)iy * Sin + jx;
#pragma unroll
                    for (int dx = 0; dx < 3; dx++) {
                        int ix = jx + dx - 1;
                        bool ok = yv && ((unsigned)ix < (unsigned)Sin);
                        vv[(dz*3+dy)*3+dx] = ok ? p[dx - 1] : 0.f;
                    }
                }
            }
            uint32_t* pah = (uint32_t*)(sAh + tid * PA);
            uint32_t* pal = (uint32_t*)(sAl + tid * PA);
#pragma unroll
            for (int j = 0; j < 13; j++) {
                float a = vv[2*j], b = vv[2*j+1];
                __half2 h = __floats2half2_rn(a, b);
                float2 hf = __half22float2(h);
                pah[j] = *(uint32_t*)&h;
                pal[j] = packh2(a - hf.x, b - hf.y);
            }
            {
                float a = vv[26];
                __half ha = __float2half_rn(a);
                __half2 h = __halves2half2(ha, __ushort_as_half(0));
                pah[13] = *(uint32_t*)&h;
                pal[13] = packh2(a - __half2float(ha), 0.f);
                pah[14] = pah[15] = 0u;
                pal[14] = pal[15] = 0u;
            }
        }
        cp_wait0();
        __syncthreads();

        // ---- load fragments
        uint32_t a_h[2][2][4], a_l[2][2][4];
#pragma unroll
        for (int mt = 0; mt < 2; mt++)
#pragma unroll
            for (int ks = 0; ks < 2; ks++) {
                int r0 = w * 32 + mt * 16 + g, r1 = r0 + 8;
                int c0 = ks * 16 + 2 * tg, c1 = c0 + 8;
                a_h[mt][ks][0] = *(uint32_t*)&sAh[r0 * PA + c0];
                a_h[mt][ks][1] = *(uint32_t*)&sAh[r1 * PA + c0];
                a_h[mt][ks][2] = *(uint32_t*)&sAh[r0 * PA + c1];
                a_h[mt][ks][3] = *(uint32_t*)&sAh[r1 * PA + c1];
                a_l[mt][ks][0] = *(uint32_t*)&sAl[r0 * PA + c0];
                a_l[mt][ks][1] = *(uint32_t*)&sAl[r1 * PA + c0];
                a_l[mt][ks][2] = *(uint32_t*)&sAl[r0 * PA + c1];
                a_l[mt][ks][3] = *(uint32_t*)&sAl[r1 * PA + c1];
            }
        uint32_t bf[8][2][2];
#pragma unroll
        for (int nt = 0; nt < 8; nt++)
#pragma unroll
            for (int ks = 0; ks < 2; ks++) {
                int rn = nt * 8 + g;
                int c0 = ks * 16 + 2 * tg;
                bf[nt][ks][0] = *(uint32_t*)&sBh[rn * PB + c0];
                bf[nt][ks][1] = *(uint32_t*)&sBh[rn * PB + c0 + 8];
            }
        // products 1+2: Ah*Bh, Al*Bh
#pragma unroll
        for (int mt = 0; mt < 2; mt++)
#pragma unroll
            for (int nt = 0; nt < 8; nt++)
#pragma unroll
                for (int ks = 0; ks < 2; ks++) {
                    MMA16816(acc[mt][nt], a_h[mt][ks], bf[nt][ks]);
                    MMA16816(acc[mt][nt], a_l[mt][ks], bf[nt][ks]);
                }
        // product 3: Ah*Bl (reuse bf regs)
#pragma unroll
        for (int nt = 0; nt < 8; nt++)
#pragma unroll
            for (int ks = 0; ks < 2; ks++) {
                int rn = nt * 8 + g;
                int c0 = ks * 16 + 2 * tg;
                bf[nt][ks][0] = *(uint32_t*)&sBl[rn * PB + c0];
                bf[nt][ks][1] = *(uint32_t*)&sBl[rn * PB + c0 + 8];
            }
#pragma unroll
        for (int mt = 0; mt < 2; mt++)
#pragma unroll
            for (int nt = 0; nt < 8; nt++)
#pragma unroll
                for (int ks = 0; ks < 2; ks++)
                    MMA16816(acc[mt][nt], a_h[mt][ks], bf[nt][ks]);
        __syncthreads();
    }

    // ---- epilogue: acc -> smem transpose -> coalesced BN+ReLU stores
#pragma unroll
    for (int mt = 0; mt < 2; mt++)
#pragma unroll
        for (int nt = 0; nt < 8; nt++) {
            int vr0 = w * 32 + mt * 16 + g, vr1 = vr0 + 8;
            int co = nt * 8 + 2 * tg;
            sT[co * 132 + vr0]       = acc[mt][nt][0];
            sT[(co + 1) * 132 + vr0] = acc[mt][nt][1];
            sT[co * 132 + vr1]       = acc[mt][nt][2];
            sT[(co + 1) * 132 + vr1] = acc[mt][nt][3];
        }
    __syncthreads();
    const float inv = rsqrtf(1.f + 1e-5f);
    const size_t S3 = (size_t)Sout * Sout * Sout;
    for (int co = 0; co < 64; co++) {
        float sc = gamma[oc0 + co] * inv, bb = beta[oc0 + co];
        float val = sT[co * 132 + tid] * sc + bb;
        out[(size_t)(oc0 + co) * S3 + vbase + tid] = fmaxf(val, 0.f);
    }
}

// ---------------------------------------------------------------- fp32 L1 (stride-1, CI=4)
template<int CI, int TY, int TXT>
__global__ void __launch_bounds__(128, 4)
conv_s1_db_kernel(const float* __restrict__ in, const float* __restrict__ wgt,
                  const float* __restrict__ gamma, const float* __restrict__ beta,
                  float* __restrict__ out, int Sin, int Sout)
{
    constexpr int TZ = 4, XPT = 8;
    constexpr int TXO = TXT * XPT;
    constexpr int HZ = TZ + 2, HY = TY + 2, HXO = TXO + 2;
    constexpr int HTOT = HZ * HY * HXO;
    constexpr int ITERS = (HTOT + 127) / 128;

    __shared__ int s_off[HTOT];
    __shared__ float s_in[2][HTOT];
    __shared__ __align__(16) float s_w[2][216];

    const int tid = threadIdx.x;
    const int lx = tid % TXT;
    const int ly = (tid / TXT) % TY;
    const int lz = tid / (TXT * TY);

    const int ntx = Sout / TXO, nty = Sout / TY;
    int bt = blockIdx.x;
    const int tx0 = (bt % ntx) * TXO; bt /= ntx;
    const int ty0 = (bt % nty) * TY;  bt /= nty;
    const int tz0 = bt * TZ;
    const int oc0 = blockIdx.y * 8;

    const int bz = tz0 - 1, by = ty0 - 1, bx = tx0 - 1;

    for (int idx = tid; idx < HTOT; idx += 128) {
        int iz = idx / (HY * HXO);
        int rem = idx - iz * (HY * HXO);
        int iy = rem / HXO;
        int ix = rem - iy * HXO;
        int gz = bz + iz, gy = by + iy, gx = bx + ix;
        int off = -1;
        if ((unsigned)gz < (unsigned)Sin && (unsigned)gy < (unsigned)Sin &&
            (unsigned)gx < (unsigned)Sin)
            off = (gz * Sin + gy) * Sin + gx;
        s_off[idx] = off;
    }

    const float* wp0 = nullptr; const float* wp1 = nullptr;
    {
        int t0 = tid >> 3, o0 = tid & 7;
        wp0 = wgt + ((size_t)(oc0 + o0) * CI) * 27 + t0;
        int i1 = tid + 128;
        if (i1 < 216) {
            int t1 = i1 >> 3, o1 = i1 & 7;
            wp1 = wgt + ((size_t)(oc0 + o1) * CI) * 27 + t1;
        }
    }
    __syncthreads();

    const size_t Sin3 = (size_t)Sin * Sin * Sin;
    unsigned sin_base = (unsigned)__cvta_generic_to_shared(&s_in[0][0]);
    unsigned sw_base  = (unsigned)__cvta_generic_to_shared(&s_w[0][0]);

    {
        const float* inc = in;
#pragma unroll
        for (int k = 0; k < ITERS; k++) {
            int idx = tid + k * 128;
            if (idx < HTOT) {
                int o = s_off[idx];
                cp4(sin_base + idx * 4, inc + (o >= 0 ? o : 0), o >= 0 ? 4u : 0u);
            }
        }
        cp4(sw_base + tid * 4, wp0, 4u);
        if (wp1) cp4(sw_base + (tid + 128) * 4, wp1, 4u);
        cp_commit();
    }

    ull acc[XPT][4];
#pragma unroll
    for (int i = 0; i < XPT; i++)
#pragma unroll
        for (int p = 0; p < 4; p++) acc[i][p] = 0ULL;

    const int iz0 = lz, iy0 = ly, ixb = lx * XPT;

    for (int ci = 0; ci < CI; ci++) {
        cp_wait0();
        __syncthreads();

        const int cur = ci & 1, nxt = cur ^ 1;
        if (ci + 1 < CI) {
            const float* inc = in + (size_t)(ci + 1) * Sin3;
            unsigned dstb = sin_base + nxt * (HTOT * 4);
#pragma unroll
            for (int k = 0; k < ITERS; k++) {
                int idx = tid + k * 128;
                if (idx < HTOT) {
                    int o = s_off[idx];
                    cp4(dstb + idx * 4, inc + (o >= 0 ? o : 0), o >= 0 ? 4u : 0u);
                }
            }
            unsigned dw = sw_base + nxt * (216 * 4);
            cp4(dw + tid * 4, wp0 + (ci + 1) * 27, 4u);
            if (wp1) cp4(dw + (tid + 128) * 4, wp1 + (ci + 1) * 27, 4u);
            cp_commit();
        } else {
            cp_commit();
        }

        const float* sbuf = &s_in[cur][0];
        const float* swb  = &s_w[cur][0];

#pragma unroll
        for (int dz = 0; dz < 3; dz++) {
#pragma unroll
            for (int dy = 0; dy < 3; dy++) {
                const float* row = &sbuf[((iz0 + dz) * HY + (iy0 + dy)) * HXO + ixb];
                ull vv[10];
#pragma unroll
                for (int j = 0; j < 10; j++) { float r = row[j]; PACK2(vv[j], r); }
#pragma unroll
                for (int dx = 0; dx < 3; dx++) {
                    const ull* wp = (const ull*)&swb[((dz * 3 + dy) * 3 + dx) * 8];
                    const ull w0 = wp[0], w1 = wp[1], w2 = wp[2], w3 = wp[3];
#pragma unroll
                    for (int xi = 0; xi < XPT; xi++) {
                        const ull vx = vv[xi + dx];
                        FMA2(acc[xi][0], vx, w0, acc[xi][0]);
                        FMA2(acc[xi][1], vx, w1, acc[xi][1]);
                        FMA2(acc[xi][2], vx, w2, acc[xi][2]);
                        FMA2(acc[xi][3], vx, w3, acc[xi][3]);
                    }
                }
            }
        }
        __syncthreads();
    }

    const int oz = tz0 + lz, oy = ty0 + ly, ox0 = tx0 + lx * XPT;
    const float inv = rsqrtf(1.f + 1e-5f);
    const size_t S3 = (size_t)Sout * Sout * Sout;
    const size_t sp = ((size_t)oz * Sout + oy) * Sout + ox0;
#pragma unroll
    for (int p = 0; p < 4; p++) {
        const int ocA = oc0 + 2 * p, ocB = ocA + 1;
        const float sA = gamma[ocA] * inv, bA = beta[ocA];
        const float sB = gamma[ocB] * inv, bB = beta[ocB];
        float lo[XPT], hi[XPT];
#pragma unroll
        for (int xi = 0; xi < XPT; xi++) {
            UNPACK2(lo[xi], hi[xi], acc[xi][p]);
            lo[xi] = fmaxf(lo[xi] * sA + bA, 0.f);
            hi[xi] = fmaxf(hi[xi] * sB + bB, 0.f);
        }
        float4* dA = (float4*)(out + (size_t)ocA * S3 + sp);
        float4* dB = (float4*)(out + (size_t)ocB * S3 + sp);
        dA[0] = make_float4(lo[0], lo[1], lo[2], lo[3]);
        dA[1] = make_float4(lo[4], lo[5], lo[6], lo[7]);
        dB[0] = make_float4(hi[0], hi[1], hi[2], hi[3]);
        dB[1] = make_float4(hi[4], hi[5], hi[6], hi[7]);
    }
}

// ---------------------------------------------------------------- BEV max + resize
__global__ void bevmax_kernel(const float* __restrict__ feat, float* __restrict__ bev) {
    int i = blockIdx.x * blockDim.x + threadIdx.x;
    if (i >= 256 * 32 * 32) return;
    int x = i & 31;
    int z = (i >> 5) & 31;
    int c = i >> 10;
    const float* p = feat + (((size_t)c * 32 + z) * 32) * 32 + x;
    float m = p[0];
#pragma unroll
    for (int y = 1; y < 32; y++) m = fmaxf(m, p[y * 32]);
    bev[i] = m;
}

__global__ void resize_kernel(const float* __restrict__ bev, float* __restrict__ out) {
    int i = blockIdx.x * blockDim.x + threadIdx.x;
    if (i >= 256 * 200 * 200) return;
    int ox = i % 200;
    int t  = i / 200;
    int oy = t % 200;
    int c  = t / 200;
    const float scale = 32.f / 200.f;
    float sy = (oy + 0.5f) * scale - 0.5f;
    float sx = (ox + 0.5f) * scale - 0.5f;
    int y0f = (int)floorf(sy); float fy = sy - (float)y0f;
    int x0f = (int)floorf(sx); float fx = sx - (float)x0f;
    int y0 = min(max(y0f, 0), 31), y1 = min(max(y0f + 1, 0), 31);
    int x0 = min(max(x0f, 0), 31), x1 = min(max(x0f + 1, 0), 31);
    const float* b = bev + (size_t)c * 1024;
    float v00 = b[y0 * 32 + x0], v01 = b[y0 * 32 + x1];
    float v10 = b[y1 * 32 + x0], v11 = b[y1 * 32 + x1];
    float v0 = v00 + (v01 - v00) * fx;
    float v1 = v10 + (v11 - v10) * fx;
    out[i] = v0 + (v1 - v0) * fy;
}

// ---------------------------------------------------------------- launch
extern "C" void kernel_launch(void* const* d_in, const int* in_sizes, int n_in,
                              void* d_out, int out_size) {
    const float* points = (const float*)d_in[0];
    const float* w[6]; const float* gm[6]; const float* bt[6];

    if (n_in >= 4 && in_sizes[2] == in_sizes[3] && in_sizes[2] <= 1024) {
        for (int i = 0; i < 6; i++) {
            w[i]  = (const float*)d_in[1 + 3*i];
            gm[i] = (const float*)d_in[2 + 3*i];
            bt[i] = (const float*)d_in[3 + 3*i];
        }
    } else {
        for (int i = 0; i < 6; i++) {
            w[i]  = (const float*)d_in[1 + i];
            gm[i] = (const float*)d_in[7 + i];
            bt[i] = (const float*)d_in[13 + i];
        }
    }
    const int N = in_sizes[0] / 4;

    float *A, *B; __half* W;
    cudaGetSymbolAddress((void**)&A, g_bufA);
    cudaGetSymbolAddress((void**)&B, g_bufB);
    cudaGetSymbolAddress((void**)&W, g_bufW);

    // weight prep (hi/lo fp16 split, tap-padded)
    __half* W2 = W;
    __half* W3 = W + 131072;
    __half* W4 = W + 393216;
    __half* W5 = W + 917504;
    __half* W6 = W + 1966080;
    prep_w_kernel<<<( 32* 64 + 255)/256, 256>>>(w[1], W2,  32,  64);
    prep_w_kernel<<<( 64* 64 + 255)/256, 256>>>(w[2], W3,  64,  64);
    prep_w_kernel<<<( 64*128 + 255)/256, 256>>>(w[3], W4,  64, 128);
    prep_w_kernel<<<(128*128 + 255)/256, 256>>>(w[4], W5, 128, 128);
    prep_w_kernel<<<(128*256 + 255)/256, 256>>>(w[5], W6, 128, 256);

    // 1. voxelize into A (4,128^3)
    const int gridElems = 4 * G3;
    zero_kernel<<<(gridElems + 255) / 256, 256>>>(A, gridElems);
    voxelize_kernel<<<(N + 255) / 256, 256>>>((const float4*)points, A, N);

    // 2. conv stack
    // L1 fp32: 4->32 s1 @128^3, A -> B
    { dim3 gr(2 * 32 * 32, 4); conv_s1_db_kernel<4, 4, 8><<<gr, 128>>>(A, w[0], gm[0], bt[0], B, 128, 128); }
    // L2 mma: 32->64 s2 -> 64^3, B -> A
    { dim3 gr(2048, 1); conv_mma_kernel< 32, 2><<<gr, 128>>>(B, W2, gm[1], bt[1], A, 128, 64,  64); }
    // L3 mma: 64->64 s1 @64^3, A -> B
    { dim3 gr(2048, 1); conv_mma_kernel< 64, 1><<<gr, 128>>>(A, W3, gm[2], bt[2], B,  64, 64,  64); }
    // L4 mma: 64->128 s2 -> 32^3, B -> A
    { dim3 gr( 256, 2); conv_mma_kernel< 64, 2><<<gr, 128>>>(B, W4, gm[3], bt[3], A,  64, 32, 128); }
    // L5 mma: 128->128 s1 @32^3, A -> B
    { dim3 gr( 256, 2); conv_mma_kernel<128, 1><<<gr, 128>>>(A, W5, gm[4], bt[4], B,  32, 32, 128); }
    // L6 mma: 128->256 s1 @32^3, B -> A
    { dim3 gr( 256, 4); conv_mma_kernel<128, 1><<<gr, 128>>>(B, W6, gm[5], bt[5], A,  32, 32, 256); }

    // 3. BEV max over y: A (256,32,32,32) -> B (256,32,32)
    bevmax_kernel<<<(256 * 32 * 32 + 255) / 256, 256>>>(A, B);

    // 4. bilinear resize to (256,200,200)
    resize_kernel<<<(256 * 200 * 200 + 255) / 256, 256>>>(B, (float*)d_out);
}

// round 7
// speedup vs baseline: 4.0290x; 1.1516x over previous
#include <cuda_runtime.h>
#include <cuda_fp16.h>
#include <math.h>
#include <stdint.h>

#define G 128
#define G3 (G*G*G)

typedef unsigned long long ull;

// ---------------- packed f32x2 helpers (fp32 L1 kernel) ----------------
#define FMA2(d, a, b, c) \
    asm("fma.rn.f32x2 %0, %1, %2, %3;" : "=l"(d) : "l"(a), "l"(b), "l"(c))
#define PACK2(d, x) \
    asm("mov.b64 %0, {%1, %2};" : "=l"(d) : "r"(__float_as_uint(x)), "r"(__float_as_uint(x)))
#define UNPACK2(lo, hi, v) \
    asm("mov.b64 {%0, %1}, %2;" : "=f"(lo), "=f"(hi) : "l"(v))

__device__ __forceinline__ void cp4(unsigned dst, const float* src, unsigned sz) {
    asm volatile("cp.async.ca.shared.global [%0], [%1], 4, %2;" :: "r"(dst), "l"(src), "r"(sz));
}
__device__ __forceinline__ void cp16(unsigned dst, const void* src) {
    asm volatile("cp.async.cg.shared.global [%0], [%1], 16;" :: "r"(dst), "l"(src));
}
__device__ __forceinline__ void cp_commit() { asm volatile("cp.async.commit_group;"); }
__device__ __forceinline__ void cp_wait0() { asm volatile("cp.async.wait_group 0;"); }

// m16n8k16 fp16 MMA, f32 accumulate
#define MMA16816(d, a, b0v, b1v) \
    asm volatile("mma.sync.aligned.m16n8k16.row.col.f32.f16.f16.f32 " \
        "{%0,%1,%2,%3}, {%4,%5,%6,%7}, {%8,%9}, {%0,%1,%2,%3};" \
        : "+f"((d)[0]), "+f"((d)[1]), "+f"((d)[2]), "+f"((d)[3]) \
        : "r"((a)[0]), "r"((a)[1]), "r"((a)[2]), "r"((a)[3]), \
          "r"(b0v), "r"(b1v))

#define LDSM4(r, addr) \
    asm volatile("ldmatrix.sync.aligned.m8n8.x4.shared.b16 {%0,%1,%2,%3}, [%4];" \
        : "=r"((r)[0]), "=r"((r)[1]), "=r"((r)[2]), "=r"((r)[3]) : "r"(addr))

__device__ __forceinline__ uint32_t packh2(float a, float b) {
    __half2 h = __floats2half2_rn(a, b);
    return *(uint32_t*)&h;
}

// ---------------- scratch buffers ----------------
__device__ float g_bufA[16777216];     // 67MB
__device__ float g_bufB[67108864];     // 268MB
__device__ __half g_bufW[4063232];     // split fp16 weights

// ---------------------------------------------------------------- utilities
__global__ void zero_kernel(float* __restrict__ p, int n) {
    int i = blockIdx.x * blockDim.x + threadIdx.x;
    if (i < n) p[i] = 0.f;
}

// ---------------------------------------------------------------- voxelize
__global__ void voxelize_kernel(const float4* __restrict__ pts, float* __restrict__ grid, int N) {
    int i = blockIdx.x * blockDim.x + threadIdx.x;
    if (i >= N) return;
    float4 p = pts[i];
    if (p.x < -32.f || p.x > 32.f ||
        p.y < -32.f || p.y > 32.f ||
        p.z < -32.f || p.z > 32.f) return;
    int cx = (int)floorf((p.x + 32.f) * 2.f);
    int cy = (int)floorf((p.y + 32.f) * 2.f);
    int cz = (int)floorf((p.z + 32.f) * 2.f);
    cx = cx < 0 ? 0 : (cx > G-1 ? G-1 : cx);
    cy = cy < 0 ? 0 : (cy > G-1 ? G-1 : cy);
    cz = cz < 0 ? 0 : (cz > G-1 ? G-1 : cz);
    int base = (cz * G + cy) * G + cx;
    atomicAdd(&grid[0*G3 + base], p.x);
    atomicAdd(&grid[1*G3 + base], p.y);
    atomicAdd(&grid[2*G3 + base], p.z);
    atomicAdd(&grid[3*G3 + base], p.w);
}

// ---------------------------------------------------------------- fused weight prep
// dst row per (ci,co): halves 0-31 = fp16_hi(taps 0-26, pad), 32-63 = fp16_lo
__global__ void prep_all_kernel(const float* __restrict__ w2, const float* __restrict__ w3,
                                const float* __restrict__ w4, const float* __restrict__ w5,
                                const float* __restrict__ w6, __half* __restrict__ dst) {
    int idx = blockIdx.x * blockDim.x + threadIdx.x;
    const float* w; int CO; size_t off;
    if (idx < 2048)            { w = w2; CO =  64; off = 0; }
    else if ((idx -= 2048) < 4096)   { w = w3; CO =  64; off = 131072; }
    else if ((idx -= 4096) < 8192)   { w = w4; CO = 128; off = 393216; }
    else if ((idx -= 8192) < 16384)  { w = w5; CO = 128; off = 917504; }
    else if ((idx -= 16384) < 32768) { w = w6; CO = 256; off = 1966080; }
    else return;
    int ci = idx / CO, co = idx - ci * CO;
    // weight layout: w[(co*CI + ci)*27 + t]; CI = pairs/CO
    // recover CI from segment: pairs = ci_max*CO; but we have w & CO; derive CI by segment sizes
    // (ci already encodes it; we only need the source row)
    const float* ws;
    if (w == w2) ws = w + ((size_t)co * 32 + ci) * 27;
    else if (w == w3) ws = w + ((size_t)co * 64 + ci) * 27;
    else if (w == w4) ws = w + ((size_t)co * 64 + ci) * 27;
    else if (w == w5) ws = w + ((size_t)co * 128 + ci) * 27;
    else ws = w + ((size_t)co * 128 + ci) * 27;

    uint32_t h2[16], l2[16];
#pragma unroll
    for (int p = 0; p < 13; p++) {
        float a = ws[2*p], b = ws[2*p+1];
        __half2 h = __floats2half2_rn(a, b);
        float2 hf = __half22float2(h);
        h2[p] = *(uint32_t*)&h;
        l2[p] = packh2(a - hf.x, b - hf.y);
    }
    {
        float a = ws[26];
        __half ha = __float2half_rn(a);
        __half2 h = __halves2half2(ha, __ushort_as_half(0));
        h2[13] = *(uint32_t*)&h;
        l2[13] = packh2(a - __half2float(ha), 0.f);
        h2[14] = h2[15] = l2[14] = l2[15] = 0u;
    }
    uint4* o = (uint4*)(dst + off + (size_t)(ci * CO + co) * 64);
    o[0] = make_uint4(h2[0], h2[1], h2[2], h2[3]);
    o[1] = make_uint4(h2[4], h2[5], h2[6], h2[7]);
    o[2] = make_uint4(h2[8], h2[9], h2[10], h2[11]);
    o[3] = make_uint4(h2[12], h2[13], h2[14], h2[15]);
    o[4] = make_uint4(l2[0], l2[1], l2[2], l2[3]);
    o[5] = make_uint4(l2[4], l2[5], l2[6], l2[7]);
    o[6] = make_uint4(l2[8], l2[9], l2[10], l2[11]);
    o[7] = make_uint4(l2[12], l2[13], l2[14], l2[15]);
}

// ---------------------------------------------------------------- mma.sync implicit-GEMM conv
// 128 voxels x NB channels per block. Rows pitch 144B: [hi 32 halves][lo 32][pad 8].
// fp16 hi/lo split, 3 products.
template<int CI, int STRIDE, int NB>
__global__ void __launch_bounds__(128)
conv_mma_kernel(const float* __restrict__ in, const __half* __restrict__ Wp,
                const float* __restrict__ gamma, const float* __restrict__ beta,
                float* __restrict__ out, int Sin, int Sout, int CO)
{
    constexpr int NT = NB / 8;
    constexpr int ASZ = 128 * 144;
    constexpr int BSZ = NB * 144;
    constexpr int EPSZ = 64 * 132 * 4;
    constexpr int SMSZ = (ASZ + BSZ) > EPSZ ? (ASZ + BSZ) : EPSZ;
    __shared__ __align__(16) char smem_raw[SMSZ];
    char* sA = smem_raw;
    char* sB = smem_raw + ASZ;
    float* sT = (float*)smem_raw;

    const int tid = threadIdx.x;
    const int w = tid >> 5, lane = tid & 31;
    const int g = lane >> 2, tg = lane & 3;

    const uint32_t uA = (uint32_t)__cvta_generic_to_shared(sA);
    const uint32_t uB = (uint32_t)__cvta_generic_to_shared(sB);
    // ldmatrix lane addressing
    const uint32_t aBase = uA + (uint32_t)((w * 32 + (lane & 15)) * 144 + (lane >> 4) * 16);
    const uint32_t bBase = uB + (uint32_t)((lane & 7) * 144 + (lane >> 3) * 16);

    const int vbase = blockIdx.x * 128;
    const int oc0 = blockIdx.y * NB;
    const int v = vbase + tid;
    const int gx = v % Sout;
    const int t1 = v / Sout;
    const int gy = t1 % Sout;
    const int gz = t1 / Sout;
    const int jx = gx * STRIDE, jy = gy * STRIDE, jz = gz * STRIDE;
    const size_t SinSq = (size_t)Sin * Sin, Sin3 = SinSq * Sin;

    float acc[2][NT][4];
#pragma unroll
    for (int mt = 0; mt < 2; mt++)
#pragma unroll
        for (int nt = 0; nt < NT; nt++)
#pragma unroll
            for (int q = 0; q < 4; q++) acc[mt][nt][q] = 0.f;

    for (int ci = 0; ci < CI; ci++) {
        // ---- stage B via cp.async: NB rows x 128B
        {
            const char* srcb = (const char*)(Wp + ((size_t)ci * CO + oc0) * 64);
            for (int u = tid; u < NB * 8; u += 128) {
                int co = u >> 3, seg = u & 7;
                cp16(uB + co * 144 + seg * 16, srcb + co * 128 + seg * 16);
            }
            cp_commit();
        }
        // ---- gather 27 taps, split hi/lo, write A row (pitch 144)
        {
            float vv[27];
#pragma unroll
            for (int dz = 0; dz < 3; dz++) {
                int iz = jz + dz - 1;
                bool zv = (unsigned)iz < (unsigned)Sin;
#pragma unroll
                for (int dy = 0; dy < 3; dy++) {
                    int iy = jy + dy - 1;
                    bool yv = zv && ((unsigned)iy < (unsigned)Sin);
                    const float* p = in + (size_t)ci * Sin3 + (size_t)iz * SinSq
                                        + (size_t)iy * Sin + jx;
#pragma unroll
                    for (int dx = 0; dx < 3; dx++) {
                        int ix = jx + dx - 1;
                        bool ok = yv && ((unsigned)ix < (unsigned)Sin);
                        vv[(dz*3+dy)*3+dx] = ok ? p[dx - 1] : 0.f;
                    }
                }
            }
            uint32_t h2[16], l2[16];
#pragma unroll
            for (int j = 0; j < 13; j++) {
                float a = vv[2*j], b = vv[2*j+1];
                __half2 h = __floats2half2_rn(a, b);
                float2 hf = __half22float2(h);
                h2[j] = *(uint32_t*)&h;
                l2[j] = packh2(a - hf.x, b - hf.y);
            }
            {
                float a = vv[26];
                __half ha = __float2half_rn(a);
                __half2 h = __halves2half2(ha, __ushort_as_half(0));
                h2[13] = *(uint32_t*)&h;
                l2[13] = packh2(a - __half2float(ha), 0.f);
                h2[14] = h2[15] = l2[14] = l2[15] = 0u;
            }
            char* rowp = sA + tid * 144;
            ((uint4*)rowp)[0] = make_uint4(h2[0], h2[1], h2[2], h2[3]);
            ((uint4*)rowp)[1] = make_uint4(h2[4], h2[5], h2[6], h2[7]);
            ((uint4*)rowp)[2] = make_uint4(h2[8], h2[9], h2[10], h2[11]);
            ((uint4*)rowp)[3] = make_uint4(h2[12], h2[13], h2[14], h2[15]);
            uint4* rowl = (uint4*)(rowp + 64);
            rowl[0] = make_uint4(l2[0], l2[1], l2[2], l2[3]);
            rowl[1] = make_uint4(l2[4], l2[5], l2[6], l2[7]);
            rowl[2] = make_uint4(l2[8], l2[9], l2[10], l2[11]);
            rowl[3] = make_uint4(l2[12], l2[13], l2[14], l2[15]);
        }
        cp_wait0();
        __syncthreads();

        // ---- fragments via ldmatrix
        uint32_t ah[2][2][4], al[2][2][4];
#pragma unroll
        for (int mt = 0; mt < 2; mt++)
#pragma unroll
            for (int ks = 0; ks < 2; ks++) {
                LDSM4(ah[mt][ks], aBase + mt * (16*144) + ks * 32);
                LDSM4(al[mt][ks], aBase + mt * (16*144) + ks * 32 + 64);
            }
#pragma unroll
        for (int nt = 0; nt < NT; nt++) {
            uint32_t bh[4], bl[4];
            LDSM4(bh, bBase + nt * (8*144));
            LDSM4(bl, bBase + nt * (8*144) + 64);
#pragma unroll
            for (int mt = 0; mt < 2; mt++) {
                MMA16816(acc[mt][nt], ah[mt][0], bh[0], bh[1]);
                MMA16816(acc[mt][nt], ah[mt][1], bh[2], bh[3]);
                MMA16816(acc[mt][nt], al[mt][0], bh[0], bh[1]);
                MMA16816(acc[mt][nt], al[mt][1], bh[2], bh[3]);
                MMA16816(acc[mt][nt], ah[mt][0], bl[0], bl[1]);
                MMA16816(acc[mt][nt], ah[mt][1], bl[2], bl[3]);
            }
        }
        __syncthreads();
    }

    // ---- epilogue: per 64-channel half: transpose via smem, coalesced BN+ReLU stores
    const float inv = rsqrtf(1.f + 1e-5f);
    const size_t S3 = (size_t)Sout * Sout * Sout;
#pragma unroll
    for (int half = 0; half < NB / 64; half++) {
        __syncthreads();
#pragma unroll
        for (int nt2 = 0; nt2 < 8; nt2++) {
            int nt = half * 8 + nt2;
#pragma unroll
            for (int mt = 0; mt < 2; mt++) {
                int vr0 = w * 32 + mt * 16 + g, vr1 = vr0 + 8;
                int co = nt2 * 8 + 2 * tg;
                sT[co * 132 + vr0]       = acc[mt][nt][0];
                sT[(co + 1) * 132 + vr0] = acc[mt][nt][1];
                sT[co * 132 + vr1]       = acc[mt][nt][2];
                sT[(co + 1) * 132 + vr1] = acc[mt][nt][3];
            }
        }
        __syncthreads();
        for (int co = 0; co < 64; co++) {
            int cog = oc0 + half * 64 + co;
            float sc = gamma[cog] * inv, bb = beta[cog];
            float val = sT[co * 132 + tid] * sc + bb;
            out[(size_t)cog * S3 + vbase + tid] = fmaxf(val, 0.f);
        }
    }
}

// ---------------------------------------------------------------- fp32 L1 (stride-1, CI=4)
template<int CI, int TY, int TXT>
__global__ void __launch_bounds__(128, 4)
conv_s1_db_kernel(const float* __restrict__ in, const float* __restrict__ wgt,
                  const float* __restrict__ gamma, const float* __restrict__ beta,
                  float* __restrict__ out, int Sin, int Sout)
{
    constexpr int TZ = 4, XPT = 8;
    constexpr int TXO = TXT * XPT;
    constexpr int HZ = TZ + 2, HY = TY + 2, HXO = TXO + 2;
    constexpr int HTOT = HZ * HY * HXO;
    constexpr int ITERS = (HTOT + 127) / 128;

    __shared__ int s_off[HTOT];
    __shared__ float s_in[2][HTOT];
    __shared__ __align__(16) float s_w[2][216];

    const int tid = threadIdx.x;
    const int lx = tid % TXT;
    const int ly = (tid / TXT) % TY;
    const int lz = tid / (TXT * TY);

    const int ntx = Sout / TXO, nty = Sout / TY;
    int bt = blockIdx.x;
    const int tx0 = (bt % ntx) * TXO; bt /= ntx;
    const int ty0 = (bt % nty) * TY;  bt /= nty;
    const int tz0 = bt * TZ;
    const int oc0 = blockIdx.y * 8;

    const int bz = tz0 - 1, by = ty0 - 1, bx = tx0 - 1;

    for (int idx = tid; idx < HTOT; idx += 128) {
        int iz = idx / (HY * HXO);
        int rem = idx - iz * (HY * HXO);
        int iy = rem / HXO;
        int ix = rem - iy * HXO;
        int gz = bz + iz, gy = by + iy, gx = bx + ix;
        int off = -1;
        if ((unsigned)gz < (unsigned)Sin && (unsigned)gy < (unsigned)Sin &&
            (unsigned)gx < (unsigned)Sin)
            off = (gz * Sin + gy) * Sin + gx;
        s_off[idx] = off;
    }

    const float* wp0 = nullptr; const float* wp1 = nullptr;
    {
        int t0 = tid >> 3, o0 = tid & 7;
        wp0 = wgt + ((size_t)(oc0 + o0) * CI) * 27 + t0;
        int i1 = tid + 128;
        if (i1 < 216) {
            int t1 = i1 >> 3, o1 = i1 & 7;
            wp1 = wgt + ((size_t)(oc0 + o1) * CI) * 27 + t1;
        }
    }
    __syncthreads();

    const size_t Sin3 = (size_t)Sin * Sin * Sin;
    unsigned sin_base = (unsigned)__cvta_generic_to_shared(&s_in[0][0]);
    unsigned sw_base  = (unsigned)__cvta_generic_to_shared(&s_w[0][0]);

    {
        const float* inc = in;
#pragma unroll
        for (int k = 0; k < ITERS; k++) {
            int idx = tid + k * 128;
            if (idx < HTOT) {
                int o = s_off[idx];
                cp4(sin_base + idx * 4, inc + (o >= 0 ? o : 0), o >= 0 ? 4u : 0u);
            }
        }
        cp4(sw_base + tid * 4, wp0, 4u);
        if (wp1) cp4(sw_base + (tid + 128) * 4, wp1, 4u);
        cp_commit();
    }

    ull acc[XPT][4];
#pragma unroll
    for (int i = 0; i < XPT; i++)
#pragma unroll
        for (int p = 0; p < 4; p++) acc[i][p] = 0ULL;

    const int iz0 = lz, iy0 = ly, ixb = lx * XPT;

    for (int ci = 0; ci < CI; ci++) {
        cp_wait0();
        __syncthreads();

        const int cur = ci & 1, nxt = cur ^ 1;
        if (ci + 1 < CI) {
            const float* inc = in + (size_t)(ci + 1) * Sin3;
            unsigned dstb = sin_base + nxt * (HTOT * 4);
#pragma unroll
            for (int k = 0; k < ITERS; k++) {
                int idx = tid + k * 128;
                if (idx < HTOT) {
                    int o = s_off[idx];
                    cp4(dstb + idx * 4, inc + (o >= 0 ? o : 0), o >= 0 ? 4u : 0u);
                }
            }
            unsigned dw = sw_base + nxt * (216 * 4);
            cp4(dw + tid * 4, wp0 + (ci + 1) * 27, 4u);
            if (wp1) cp4(dw + (tid + 128) * 4, wp1 + (ci + 1) * 27, 4u);
            cp_commit();
        } else {
            cp_commit();
        }

        const float* sbuf = &s_in[cur][0];
        const float* swb  = &s_w[cur][0];

#pragma unroll
        for (int dz = 0; dz < 3; dz++) {
#pragma unroll
            for (int dy = 0; dy < 3; dy++) {
                const float* row = &sbuf[((iz0 + dz) * HY + (iy0 + dy)) * HXO + ixb];
                ull vv[10];
#pragma unroll
                for (int j = 0; j < 10; j++) { float r = row[j]; PACK2(vv[j], r); }
#pragma unroll
                for (int dx = 0; dx < 3; dx++) {
                    const ull* wp = (const ull*)&swb[((dz * 3 + dy) * 3 + dx) * 8];
                    const ull w0 = wp[0], w1 = wp[1], w2 = wp[2], w3 = wp[3];
#pragma unroll
                    for (int xi = 0; xi < XPT; xi++) {
                        const ull vx = vv[xi + dx];
                        FMA2(acc[xi][0], vx, w0, acc[xi][0]);
                        FMA2(acc[xi][1], vx, w1, acc[xi][1]);
                        FMA2(acc[xi][2], vx, w2, acc[xi][2]);
                        FMA2(acc[xi][3], vx, w3, acc[xi][3]);
                    }
                }
            }
        }
        __syncthreads();
    }

    const int oz = tz0 + lz, oy = ty0 + ly, ox0 = tx0 + lx * XPT;
    const float inv = rsqrtf(1.f + 1e-5f);
    const size_t S3 = (size_t)Sout * Sout * Sout;
    const size_t sp = ((size_t)oz * Sout + oy) * Sout + ox0;
#pragma unroll
    for (int p = 0; p < 4; p++) {
        const int ocA = oc0 + 2 * p, ocB = ocA + 1;
        const float sA = gamma[ocA] * inv, bA = beta[ocA];
        const float sB = gamma[ocB] * inv, bB = beta[ocB];
        float lo[XPT], hi[XPT];
#pragma unroll
        for (int xi = 0; xi < XPT; xi++) {
            UNPACK2(lo[xi], hi[xi], acc[xi][p]);
            lo[xi] = fmaxf(lo[xi] * sA + bA, 0.f);
            hi[xi] = fmaxf(hi[xi] * sB + bB, 0.f);
        }
        float4* dA = (float4*)(out + (size_t)ocA * S3 + sp);
        float4* dB = (float4*)(out + (size_t)ocB * S3 + sp);
        dA[0] = make_float4(lo[0], lo[1], lo[2], lo[3]);
        dA[1] = make_float4(lo[4], lo[5], lo[6], lo[7]);
        dB[0] = make_float4(hi[0], hi[1], hi[2], hi[3]);
        dB[1] = make_float4(hi[4], hi[5], hi[6], hi[7]);
    }
}

// ---------------------------------------------------------------- BEV max + resize
__global__ void bevmax_kernel(const float* __restrict__ feat, float* __restrict__ bev) {
    int i = blockIdx.x * blockDim.x + threadIdx.x;
    if (i >= 256 * 32 * 32) return;
    int x = i & 31;
    int z = (i >> 5) & 31;
    int c = i >> 10;
    const float* p = feat + (((size_t)c * 32 + z) * 32) * 32 + x;
    float m = p[0];
#pragma unroll
    for (int y = 1; y < 32; y++) m = fmaxf(m, p[y * 32]);
    bev[i] = m;
}

__global__ void resize_kernel(const float* __restrict__ bev, float* __restrict__ out) {
    int i = blockIdx.x * blockDim.x + threadIdx.x;
    if (i >= 256 * 200 * 200) return;
    int ox = i % 200;
    int t  = i / 200;
    int oy = t % 200;
    int c  = t / 200;
    const float scale = 32.f / 200.f;
    float sy = (oy + 0.5f) * scale - 0.5f;
    float sx = (ox + 0.5f) * scale - 0.5f;
    int y0f = (int)floorf(sy); float fy = sy - (float)y0f;
    int x0f = (int)floorf(sx); float fx = sx - (float)x0f;
    int y0 = min(max(y0f, 0), 31), y1 = min(max(y0f + 1, 0), 31);
    int x0 = min(max(x0f, 0), 31), x1 = min(max(x0f + 1, 0), 31);
    const float* b = bev + (size_t)c * 1024;
    float v00 = b[y0 * 32 + x0], v01 = b[y0 * 32 + x1];
    float v10 = b[y1 * 32 + x0], v11 = b[y1 * 32 + x1];
    float v0 = v00 + (v01 - v00) * fx;
    float v1 = v10 + (v11 - v10) * fx;
    out[i] = v0 + (v1 - v0) * fy;
}

// ---------------------------------------------------------------- launch
extern "C" void kernel_launch(void* const* d_in, const int* in_sizes, int n_in,
                              void* d_out, int out_size) {
    const float* points = (const float*)d_in[0];
    const float* w[6]; const float* gm[6]; const float* bt[6];

    if (n_in >= 4 && in_sizes[2] == in_sizes[3] && in_sizes[2] <= 1024) {
        for (int i = 0; i < 6; i++) {
            w[i]  = (const float*)d_in[1 + 3*i];
            gm[i] = (const float*)d_in[2 + 3*i];
            bt[i] = (const float*)d_in[3 + 3*i];
        }
    } else {
        for (int i = 0; i < 6; i++) {
            w[i]  = (const float*)d_in[1 + i];
            gm[i] = (const float*)d_in[7 + i];
            bt[i] = (const float*)d_in[13 + i];
        }
    }
    const int N = in_sizes[0] / 4;

    float *A, *B; __half* W;
    cudaGetSymbolAddress((void**)&A, g_bufA);
    cudaGetSymbolAddress((void**)&B, g_bufB);
    cudaGetSymbolAddress((void**)&W, g_bufW);

    // fused weight prep (hi/lo fp16 split)
    prep_all_kernel<<<496, 128>>>(w[1], w[2], w[3], w[4], w[5], W);
    __half* W2 = W;
    __half* W3 = W + 131072;
    __half* W4 = W + 393216;
    __half* W5 = W + 917504;
    __half* W6 = W + 1966080;

    // 1. voxelize into A (4,128^3)
    const int gridElems = 4 * G3;
    zero_kernel<<<(gridElems + 255) / 256, 256>>>(A, gridElems);
    voxelize_kernel<<<(N + 255) / 256, 256>>>((const float4*)points, A, N);

    // 2. conv stack
    // L1 fp32: 4->32 s1 @128^3, A -> B
    { dim3 gr(2 * 32 * 32, 4); conv_s1_db_kernel<4, 4, 8><<<gr, 128>>>(A, w[0], gm[0], bt[0], B, 128, 128); }
    // L2 mma: 32->64 s2 -> 64^3, B -> A
    { dim3 gr(2048, 1); conv_mma_kernel< 32, 2,  64><<<gr, 128>>>(B, W2, gm[1], bt[1], A, 128, 64,  64); }
    // L3 mma: 64->64 s1 @64^3, A -> B
    { dim3 gr(2048, 1); conv_mma_kernel< 64, 1,  64><<<gr, 128>>>(A, W3, gm[2], bt[2], B,  64, 64,  64); }
    // L4 mma: 64->128 s2 -> 32^3, B -> A  (NB=128, single gather)
    { dim3 gr( 256, 1); conv_mma_kernel< 64, 2, 128><<<gr, 128>>>(B, W4, gm[3], bt[3], A,  64, 32, 128); }
    // L5 mma: 128->128 s1 @32^3, A -> B
    { dim3 gr( 256, 1); conv_mma_kernel<128, 1, 128><<<gr, 128>>>(A, W5, gm[4], bt[4], B,  32, 32, 128); }
    // L6 mma: 128->256 s1 @32^3, B -> A
    { dim3 gr( 256, 2); conv_mma_kernel<128, 1, 128><<<gr, 128>>>(B, W6, gm[5], bt[5], A,  32, 32, 256); }

    // 3. BEV max over y: A (256,32,32,32) -> B (256,32,32)
    bevmax_kernel<<<(256 * 32 * 32 + 255) / 256, 256>>>(A, B);

    // 4. bilinear resize to (256,200,200)
    resize_kernel<<<(256 * 200 * 200 + 255) / 256, 256>>>(B, (float*)d_out);
}